// round 15
// baseline (speedup 1.0000x reference)
#include <cuda_runtime.h>
#include <cuda_fp16.h>
#include <cstdint>

#define DIM 128
#define MSZ (DIM * DIM)
#define NCTA 148

// fp32 tables for direct copies: g_U[e] = map for pos e+1, e in [0,254]
__device__ __align__(16) float g_U[255 * MSZ];
// fp16 images, chunked SW128 layout:
//  g_A16[s] : T_8[s] (pos 256+s), [m][k], HI ONLY (32KB)
//  g_B16[e] : entry e, [n][k], hi+lo (64KB)
//  g_AW[b]  : T_1[b] = W_b^T, [m][k], hi+lo
//  g_AT2[s] : T_2[s] [m][k] hi+lo ;  g_AT4[s] : T_4[s] [m][k] hi+lo
__device__ __align__(1024) __half g_A16[256 * 16384];
__device__ __align__(1024) __half g_B16[255 * 32768];
__device__ __align__(1024) __half g_AW[2 * 32768];
__device__ __align__(1024) __half g_AT2[4 * 32768];
__device__ __align__(1024) __half g_AT4[16 * 32768];
// expm scratch
__device__ __align__(16) float g_Bm[2 * MSZ];
__device__ __align__(16) float g_B2[2 * MSZ];
__device__ __align__(16) float g_B3[2 * MSZ];
__device__ __align__(16) float g_B4[2 * MSZ];
__device__ __align__(16) float g_X0[2 * MSZ];
__device__ __align__(16) float g_X1[2 * MSZ];
// dataflow state (monotonic across graph replays; epoch-tagged)
__device__ unsigned g_count = 0;
__device__ unsigned g_epoch = 0;
__device__ unsigned g_flag[511];
__device__ unsigned g_oflag = 0;
__device__ unsigned g_done = 0;        // completed phase-B tasks (508 per epoch)
__device__ int g_order[8192];

#define SW128(o) ((o) ^ (((o) >> 3) & 0x70))
#define STRIDE_S 132                    // padded stage row stride (floats)

// ------------------------------------------------------------- PTX helpers
__device__ __forceinline__ uint32_t smem_to_u32(const void* p) {
    uint32_t a;
    asm("{ .reg .u64 t; cvta.to.shared.u64 t, %1; cvt.u32.u64 %0, t; }" : "=r"(a) : "l"(p));
    return a;
}
#define MBARRIER_INIT(addr, cnt) \
    asm volatile("mbarrier.init.shared.b64 [%0], %1;" :: "r"((uint32_t)(addr)), "r"((uint32_t)(cnt)) : "memory")
#define MBARRIER_EXPECT_TX(addr, tx) \
    asm volatile("mbarrier.arrive.expect_tx.shared.b64 _, [%0], %1;" :: "r"((uint32_t)(addr)), "r"((uint32_t)(tx)) : "memory")
#define MBARRIER_ARRIVE(addr) \
    asm volatile("mbarrier.arrive.shared.b64 _, [%0];" :: "r"((uint32_t)(addr)) : "memory")
#define MBARRIER_WAIT_PARITY(mbar_smem_addr, phase_parity) do { \
    uint32_t _mbar = (uint32_t)(mbar_smem_addr); \
    uint32_t _parity = (uint32_t)(phase_parity); \
    uint32_t _done; \
    asm volatile("{\n\t.reg .pred p;\n\t" \
        "mbarrier.try_wait.parity.acquire.cta.shared::cta.b64 p, [%1], %2;\n\t" \
        "selp.b32 %0, 1, 0, p;\n\t}" : "=r"(_done) : "r"(_mbar), "r"(_parity) : "memory"); \
    if (!_done) { \
        asm volatile("{\n\t.reg .pred P1;\n\t" \
            "WAIT_LOOP_%=:\n\t" \
            "mbarrier.try_wait.parity.acquire.cta.shared::cta.b64 P1, [%0], %1, 0x989680;\n\t" \
            "@P1 bra.uni WAIT_DONE_%=;\n\t" \
            "bra.uni WAIT_LOOP_%=;\n\t" \
            "WAIT_DONE_%=:\n\t}" :: "r"(_mbar), "r"(_parity) : "memory"); \
    } \
} while (0)
__device__ __forceinline__ void bulk_ld(uint32_t dst, const void* src, uint32_t bytes, uint32_t mbar) {
    asm volatile("cp.async.bulk.shared::cta.global.mbarrier::complete_tx::bytes [%0], [%1], %2, [%3];"
                 :: "r"(dst), "l"(src), "r"(bytes), "r"(mbar) : "memory");
}
#define LDSM4(r0, r1, r2, r3, a) \
    asm volatile("ldmatrix.sync.aligned.m8n8.x4.shared.b16 {%0,%1,%2,%3}, [%4];" \
                 : "=r"(r0), "=r"(r1), "=r"(r2), "=r"(r3) : "r"(a))
#define MMA16816(c0, c1, c2, c3, a0, a1, a2, a3, b0, b1) \
    asm volatile("mma.sync.aligned.m16n8k16.row.col.f32.f16.f16.f32 " \
                 "{%0,%1,%2,%3}, {%4,%5,%6,%7}, {%8,%9}, {%0,%1,%2,%3};" \
                 : "+f"(c0), "+f"(c1), "+f"(c2), "+f"(c3) \
                 : "r"(a0), "r"(a1), "r"(a2), "r"(a3), "r"(b0), "r"(b1))

#define BAR_A() asm volatile("bar.sync 2, 256;" ::: "memory")

// hi/lo fp16 split write into a SW128 image
__device__ __forceinline__ void img_put(__half* img, int row, int k, float v) {
    int idx = ((k >> 6) << 13) + (SW128(row * 128 + (k & 63) * 2) >> 1);
    __half h = __float2half_rn(v);
    img[idx] = h;
    img[idx + 16384] = __float2half_rn(v - __half2float(h));
}

// --------------------------------------------- epoch-tagged ready flags
__device__ __forceinline__ void flag_set(int e, unsigned E) {
    asm volatile("fence.proxy.async;" ::: "memory");
    __threadfence();
    asm volatile("st.release.gpu.u32 [%0], %1;" :: "l"(&g_flag[e]), "r"(E) : "memory");
}
__device__ __forceinline__ void flag_wait(int e, unsigned E) {
    unsigned v;
    do {
        asm volatile("ld.acquire.gpu.u32 %0, [%1];" : "=r"(v) : "l"(&g_flag[e]) : "memory");
        if ((int)(v - E) >= 0) break;
        __nanosleep(32);
    } while (true);
}
__device__ __forceinline__ void uflag_wait(unsigned* p, unsigned E) {
    unsigned v;
    do {
        asm volatile("ld.acquire.gpu.u32 %0, [%1];" : "=r"(v) : "l"(p) : "memory");
        if ((int)(v - E) >= 0) break;
        __nanosleep(32);
    } while (true);
}
__device__ __forceinline__ void done_add() {
    unsigned one = 1;
    asm volatile("red.release.gpu.global.add.u32 [%0], %1;" :: "l"(&g_done), "r"(one) : "memory");
}
__device__ __forceinline__ int all_done(unsigned E) {
    unsigned v;
    asm volatile("ld.acquire.gpu.u32 %0, [%1];" : "=r"(v) : "l"(&g_done) : "memory");
    return (int)(v - 508u * E) >= 0;
}

// --------------------------------------- 32-CTA spin barrier (expm, t<256)
__device__ __forceinline__ void gbar32(unsigned target) {
    BAR_A();
    if (threadIdx.x == 0) {
        __threadfence();
        atomicAdd(&g_count, 1u);
        unsigned v;
        do {
            asm volatile("ld.acquire.gpu.u32 %0, [%1];" : "=r"(v) : "l"(&g_count) : "memory");
            if ((int)(v - target) >= 0) break;
            __nanosleep(32);
        } while (true);
    }
    BAR_A();
}

// --------------------- fp32 32x32 tile engine (named barrier, 256 threads)
__device__ __forceinline__ void mm32nb(const float* __restrict__ A, const float* __restrict__ B,
                                       int rowBase, int colBase, float acc[2][2]) {
    __shared__ __align__(16) float As[16][33];
    __shared__ __align__(16) float Bs[16][33];
    int t = threadIdx.x;
    int tx = t & 15, ty = t >> 4;
    acc[0][0] = acc[0][1] = acc[1][0] = acc[1][1] = 0.0f;
    for (int kc = 0; kc < DIM; kc += 16) {
        {
            int ar = t >> 3, ac = (t & 7) * 2;
            float2 av = __ldcg((const float2*)&A[(rowBase + ar) * DIM + kc + ac]);
            As[ac][ar] = av.x; As[ac + 1][ar] = av.y;
        }
        {
            int br = t >> 4, bc = (t & 15) * 2;
            float2 bv = __ldcg((const float2*)&B[(kc + br) * DIM + colBase + bc]);
            Bs[br][bc] = bv.x; Bs[br][bc + 1] = bv.y;
        }
        BAR_A();
#pragma unroll
        for (int kk = 0; kk < 16; kk++) {
            float a0 = As[kk][ty * 2], a1 = As[kk][ty * 2 + 1];
            float b0 = Bs[kk][tx * 2], b1 = Bs[kk][tx * 2 + 1];
            acc[0][0] += a0 * b0; acc[0][1] += a0 * b1;
            acc[1][0] += a1 * b0; acc[1][1] += a1 * b1;
        }
        BAR_A();
    }
}
// PS-fused variant: A operand computed inline as c12 I + c13 B + c14 B2 + c15 B3 + c16 B4.
__device__ __forceinline__ void mm32ps(const float* __restrict__ Bm, const float* __restrict__ B2,
                                       const float* __restrict__ B3, const float* __restrict__ B4,
                                       int rowBase, int colBase, float acc[2][2]) {
    const float c12 = 2.08767570e-9f, c13 = 1.60590438e-10f, c14 = 1.14707456e-11f,
                c15 = 7.64716373e-13f, c16 = 4.77947733e-14f;
    __shared__ __align__(16) float As[16][33];
    __shared__ __align__(16) float Bs[16][33];
    int t = threadIdx.x;
    int tx = t & 15, ty = t >> 4;
    acc[0][0] = acc[0][1] = acc[1][0] = acc[1][1] = 0.0f;
    for (int kc = 0; kc < DIM; kc += 16) {
        {
            int ar = t >> 3, ac = (t & 7) * 2;
            int row = rowBase + ar;
            int e = row * DIM + kc + ac;
            float2 v1 = __ldcg((const float2*)&Bm[e]);
            float2 v2 = __ldcg((const float2*)&B2[e]);
            float2 v3 = __ldcg((const float2*)&B3[e]);
            float2 v4 = __ldcg((const float2*)&B4[e]);
            float vx = c13 * v1.x + c14 * v2.x + c15 * v3.x + c16 * v4.x;
            float vy = c13 * v1.y + c14 * v2.y + c15 * v3.y + c16 * v4.y;
            if (row == kc + ac) vx += c12;
            if (row == kc + ac + 1) vy += c12;
            As[ac][ar] = vx; As[ac + 1][ar] = vy;
        }
        {
            int br = t >> 4, bc = (t & 15) * 2;
            float2 bv = __ldcg((const float2*)&B4[(kc + br) * DIM + colBase + bc]);
            Bs[br][bc] = bv.x; Bs[br][bc + 1] = bv.y;
        }
        BAR_A();
#pragma unroll
        for (int kk = 0; kk < 16; kk++) {
            float a0 = As[kk][ty * 2], a1 = As[kk][ty * 2 + 1];
            float b0 = Bs[kk][tx * 2], b1 = Bs[kk][tx * 2 + 1];
            acc[0][0] += a0 * b0; acc[0][1] += a0 * b1;
            acc[1][0] += a1 * b0; acc[1][1] += a1 * b1;
        }
        BAR_A();
    }
}
__device__ __forceinline__ void store32(float* __restrict__ C, int rowBase, int colBase,
                                        float acc[2][2]) {
    int tx = threadIdx.x & 15, ty = threadIdx.x >> 4;
#pragma unroll
    for (int i = 0; i < 2; i++)
#pragma unroll
        for (int j = 0; j < 2; j++)
            C[(rowBase + ty * 2 + i) * DIM + colBase + tx * 2 + j] = acc[i][j];
}

// ---------------------------------------------------------------------------
// prodS: warp tile 32x32 single product (wr 0..3, wc 0..3), 16 warps.
// ---------------------------------------------------------------------------
__device__ __forceinline__ void prodS(uint32_t aimg, uint32_t bimg,
                                      int wr, int wc, int lane, float acc[2][4][4]) {
    int rA = (wr * 32 + (lane & 15)) * 128;
    int seg = (lane >> 4) * 16;
    int rB = (wc * 32 + (lane & 15)) * 128;
#pragma unroll
    for (int ks = 0; ks < 8; ks++) {
        uint32_t coff = (uint32_t)(ks >> 2) * 16384u;
        int kw2 = (ks & 3) * 32;
        uint32_t a0[4], a1[4], b0[4], b1[4];
        LDSM4(a0[0], a0[1], a0[2], a0[3], aimg + coff + (uint32_t)SW128(rA + kw2 + seg));
        LDSM4(a1[0], a1[1], a1[2], a1[3], aimg + coff + (uint32_t)SW128(rA + 2048 + kw2 + seg));
        LDSM4(b0[0], b0[1], b0[2], b0[3], bimg + coff + (uint32_t)SW128(rB + kw2 + seg));
        LDSM4(b1[0], b1[1], b1[2], b1[3], bimg + coff + (uint32_t)SW128(rB + 2048 + kw2 + seg));
        MMA16816(acc[0][0][0], acc[0][0][1], acc[0][0][2], acc[0][0][3],
                 a0[0], a0[1], a0[2], a0[3], b0[0], b0[2]);
        MMA16816(acc[0][1][0], acc[0][1][1], acc[0][1][2], acc[0][1][3],
                 a0[0], a0[1], a0[2], a0[3], b0[1], b0[3]);
        MMA16816(acc[0][2][0], acc[0][2][1], acc[0][2][2], acc[0][2][3],
                 a0[0], a0[1], a0[2], a0[3], b1[0], b1[2]);
        MMA16816(acc[0][3][0], acc[0][3][1], acc[0][3][2], acc[0][3][3],
                 a0[0], a0[1], a0[2], a0[3], b1[1], b1[3]);
        MMA16816(acc[1][0][0], acc[1][0][1], acc[1][0][2], acc[1][0][3],
                 a1[0], a1[1], a1[2], a1[3], b0[0], b0[2]);
        MMA16816(acc[1][1][0], acc[1][1][1], acc[1][1][2], acc[1][1][3],
                 a1[0], a1[1], a1[2], a1[3], b0[1], b0[3]);
        MMA16816(acc[1][2][0], acc[1][2][1], acc[1][2][2], acc[1][2][3],
                 a1[0], a1[1], a1[2], a1[3], b1[0], b1[2]);
        MMA16816(acc[1][3][0], acc[1][3][1], acc[1][3][2], acc[1][3][3],
                 a1[0], a1[1], a1[2], a1[3], b1[1], b1[3]);
    }
}
// paired: A fragments shared across two B images (two positions, same A)
__device__ __forceinline__ void prodS2(uint32_t aimg, uint32_t b0img, uint32_t b1img,
                                       int wr, int wc, int lane, int pair,
                                       float acc0[2][4][4], float acc1[2][4][4]) {
    int rA = (wr * 32 + (lane & 15)) * 128;
    int seg = (lane >> 4) * 16;
    int rB = (wc * 32 + (lane & 15)) * 128;
#pragma unroll
    for (int ks = 0; ks < 8; ks++) {
        uint32_t coff = (uint32_t)(ks >> 2) * 16384u;
        int kw2 = (ks & 3) * 32;
        uint32_t bo0 = coff + (uint32_t)SW128(rB + kw2 + seg);
        uint32_t bo1 = coff + (uint32_t)SW128(rB + 2048 + kw2 + seg);
        uint32_t a0[4], a1[4], b0[4], b1[4];
        LDSM4(a0[0], a0[1], a0[2], a0[3], aimg + coff + (uint32_t)SW128(rA + kw2 + seg));
        LDSM4(a1[0], a1[1], a1[2], a1[3], aimg + coff + (uint32_t)SW128(rA + 2048 + kw2 + seg));
        LDSM4(b0[0], b0[1], b0[2], b0[3], b0img + bo0);
        LDSM4(b1[0], b1[1], b1[2], b1[3], b0img + bo1);
        MMA16816(acc0[0][0][0], acc0[0][0][1], acc0[0][0][2], acc0[0][0][3],
                 a0[0], a0[1], a0[2], a0[3], b0[0], b0[2]);
        MMA16816(acc0[0][1][0], acc0[0][1][1], acc0[0][1][2], acc0[0][1][3],
                 a0[0], a0[1], a0[2], a0[3], b0[1], b0[3]);
        MMA16816(acc0[0][2][0], acc0[0][2][1], acc0[0][2][2], acc0[0][2][3],
                 a0[0], a0[1], a0[2], a0[3], b1[0], b1[2]);
        MMA16816(acc0[0][3][0], acc0[0][3][1], acc0[0][3][2], acc0[0][3][3],
                 a0[0], a0[1], a0[2], a0[3], b1[1], b1[3]);
        MMA16816(acc0[1][0][0], acc0[1][0][1], acc0[1][0][2], acc0[1][0][3],
                 a1[0], a1[1], a1[2], a1[3], b0[0], b0[2]);
        MMA16816(acc0[1][1][0], acc0[1][1][1], acc0[1][1][2], acc0[1][1][3],
                 a1[0], a1[1], a1[2], a1[3], b0[1], b0[3]);
        MMA16816(acc0[1][2][0], acc0[1][2][1], acc0[1][2][2], acc0[1][2][3],
                 a1[0], a1[1], a1[2], a1[3], b1[0], b1[2]);
        MMA16816(acc0[1][3][0], acc0[1][3][1], acc0[1][3][2], acc0[1][3][3],
                 a1[0], a1[1], a1[2], a1[3], b1[1], b1[3]);
        if (pair) {
            LDSM4(b0[0], b0[1], b0[2], b0[3], b1img + bo0);
            LDSM4(b1[0], b1[1], b1[2], b1[3], b1img + bo1);
            MMA16816(acc1[0][0][0], acc1[0][0][1], acc1[0][0][2], acc1[0][0][3],
                     a0[0], a0[1], a0[2], a0[3], b0[0], b0[2]);
            MMA16816(acc1[0][1][0], acc1[0][1][1], acc1[0][1][2], acc1[0][1][3],
                     a0[0], a0[1], a0[2], a0[3], b0[1], b0[3]);
            MMA16816(acc1[0][2][0], acc1[0][2][1], acc1[0][2][2], acc1[0][2][3],
                     a0[0], a0[1], a0[2], a0[3], b1[0], b1[2]);
            MMA16816(acc1[0][3][0], acc1[0][3][1], acc1[0][3][2], acc1[0][3][3],
                     a0[0], a0[1], a0[2], a0[3], b1[1], b1[3]);
            MMA16816(acc1[1][0][0], acc1[1][0][1], acc1[1][0][2], acc1[1][0][3],
                     a1[0], a1[1], a1[2], a1[3], b0[0], b0[2]);
            MMA16816(acc1[1][1][0], acc1[1][1][1], acc1[1][1][2], acc1[1][1][3],
                     a1[0], a1[1], a1[2], a1[3], b0[1], b0[3]);
            MMA16816(acc1[1][2][0], acc1[1][2][1], acc1[1][2][2], acc1[1][2][3],
                     a1[0], a1[1], a1[2], a1[3], b1[0], b1[2]);
            MMA16816(acc1[1][3][0], acc1[1][3][1], acc1[1][3][2], acc1[1][3][3],
                     a1[0], a1[1], a1[2], a1[3], b1[1], b1[3]);
        }
    }
}
__device__ __forceinline__ void store_fragS(float* __restrict__ C, int wr, int wc, int lane,
                                            float acc[2][4][4]) {
#pragma unroll
    for (int at = 0; at < 2; at++) {
        int row0 = wr * 32 + at * 16 + (lane >> 2);
#pragma unroll
        for (int ct = 0; ct < 4; ct++) {
            int col = wc * 32 + ct * 8 + (lane & 3) * 2;
            *(float2*)&C[row0 * DIM + col]       = make_float2(acc[at][ct][0], acc[at][ct][1]);
            *(float2*)&C[(row0 + 8) * DIM + col] = make_float2(acc[at][ct][2], acc[at][ct][3]);
        }
    }
}
// stage into padded smem (row stride 132 floats) to de-amplify global stores
__device__ __forceinline__ void stage_fragS(float* __restrict__ S, int wr, int wc, int lane,
                                            float acc[2][4][4]) {
#pragma unroll
    for (int at = 0; at < 2; at++) {
        int row0 = wr * 32 + at * 16 + (lane >> 2);
#pragma unroll
        for (int ct = 0; ct < 4; ct++) {
            int col = wc * 32 + ct * 8 + (lane & 3) * 2;
            *(float2*)&S[row0 * STRIDE_S + col]       = make_float2(acc[at][ct][0], acc[at][ct][1]);
            *(float2*)&S[(row0 + 8) * STRIDE_S + col] = make_float2(acc[at][ct][2], acc[at][ct][3]);
        }
    }
}
// coalesced flush: stage (padded) -> contiguous global
__device__ __forceinline__ void flushC(const float* __restrict__ S, float* __restrict__ C, int t) {
#pragma unroll
    for (int it = 0; it < 8; it++) {
        int e = t * 4 + it * 2048;
        int row = e >> 7, col = e & 127;
        float4 v = *(const float4*)&S[row * STRIDE_S + col];
        *(float4*)&C[e] = v;
    }
}

__global__ void k_epoch() { atomicAdd(&g_epoch, 1u); }

// ===========================================================================
// k_mega: ONE dataflow kernel, 512 threads.
//   Phase A (CTAs 0-31, t<256): expm (s=5, PS deg 16 fused-init, 5 squarings).
//   CTA 32: counting-sort positions by (pos & 255) -> g_order.
//   Phase B (all CTAs): 508 doubling tasks, gated by parent flags; g_done++.
//   Phase C: sorted chunks, paired A-reuse HMMA, smem-staged coalesced output.
// ===========================================================================
#define NBARE 12u
#define HDR 3072
#define SLOT_SZ 98304
#define MEGA_SMEM (HDR + 2 * SLOT_SZ)

__device__ __forceinline__ void load_unit(uint32_t sb, int slot, int rr, int q0, int q1,
                                          unsigned E, int skip) {
    if (!skip) {
        flag_wait(255 + rr, E);
        flag_wait(q0, E);
        if (q1 != q0) flag_wait(q1, E);
    }
    uint32_t mb = sb + (uint32_t)slot * 16;
    MBARRIER_EXPECT_TX(mb, 98304);
    uint32_t dst = sb + HDR + (uint32_t)slot * SLOT_SZ;
    bulk_ld(dst,         g_A16 + (size_t)rr * 16384, 32768, mb);
    bulk_ld(dst + 32768, g_B16 + (size_t)q0 * 32768, 32768, mb);
    bulk_ld(dst + 65536, g_B16 + (size_t)q1 * 32768, 32768, mb);
}

__global__ void __launch_bounds__(512, 1) k_mega(const int* __restrict__ uniq,
                                                 const float* __restrict__ P,
                                                 float* __restrict__ out, int n) {
    extern __shared__ char smem[];
    uint32_t sb = smem_to_u32(smem);
    const int t = threadIdx.x;
    const int cta = blockIdx.x;
    __shared__ unsigned sE;
    __shared__ int s_cnt[2];
    if (t == 0) {
#pragma unroll
        for (int s = 0; s < 2; s++) {
            MBARRIER_INIT(sb + s * 16, 1);        // slot full
            MBARRIER_INIT(sb + s * 16 + 8, 512);  // slot empty
        }
        MBARRIER_INIT(sb + 64, 1);                // phase-B hi
        MBARRIER_INIT(sb + 72, 1);                // phase-B lo
        sE = *(volatile unsigned*)&g_epoch;
    }
    __syncthreads();
    const unsigned E = sE;

    // ================= Phase A: expm (CTAs 0-31, threads < 256) =================
    if (cta < 32 && t < 256) {
        const unsigned baseE = (E - 1u) * NBARE * 32u;
        int barId = 0;
#define GB32() gbar32(baseE + (unsigned)(++barId) * 32u)
        const float c0 = 1.0f, c1 = 1.0f, c2 = 0.5f, c3 = 1.0f / 6.0f, c4 = 1.0f / 24.0f;
        const float c5 = 1.0f / 120.0f, c6 = 1.0f / 720.0f, c7 = 1.0f / 5040.0f;
        const float c8 = 1.0f / 40320.0f, c9 = 2.75573192e-6f, c10 = 2.75573192e-7f;
        const float c11 = 2.50521084e-8f;

        const int b = cta >> 4, tile = cta & 15;
        const int rB = (tile >> 2) * 32, cB = (tile & 3) * 32;

        for (int idx = cta * 256 + t; idx < 2 * MSZ; idx += 8192) {
            int bb = idx >> 14, r = (idx >> 7) & 127, c = idx & 127;
            float h = __ldg(&P[bb * MSZ + r * DIM + c]) - __ldg(&P[bb * MSZ + c * DIM + r]);
            g_Bm[idx] = h * (1.0f / 32.0f);          // s = 5
        }
        GB32();
        {
            float acc[2][2];
            mm32nb(g_Bm + b * MSZ, g_Bm + b * MSZ, rB, cB, acc);
            store32(g_B2 + b * MSZ, rB, cB, acc);
        }
        GB32();
        {
            float acc[2][2];
            mm32nb(g_B2 + b * MSZ, g_Bm + b * MSZ, rB, cB, acc);
            store32(g_B3 + b * MSZ, rB, cB, acc);
            float acc2[2][2];
            mm32nb(g_B2 + b * MSZ, g_B2 + b * MSZ, rB, cB, acc2);
            store32(g_B4 + b * MSZ, rB, cB, acc2);
        }
        GB32();
        {   // h1 with PS-init fused into the A-operand load
            float acc[2][2];
            mm32ps(g_Bm + b * MSZ, g_B2 + b * MSZ, g_B3 + b * MSZ, g_B4 + b * MSZ,
                   rB, cB, acc);
            int tx = t & 15, ty = t >> 4;
#pragma unroll
            for (int i = 0; i < 2; i++) {
                int gr = rB + ty * 2 + i;
#pragma unroll
                for (int j = 0; j < 2; j++) {
                    int gc = cB + tx * 2 + j;
                    int e = b * MSZ + gr * DIM + gc;
                    float v = acc[i][j] + c9 * __ldcg(&g_Bm[e]) +
                              c10 * __ldcg(&g_B2[e]) + c11 * __ldcg(&g_B3[e]);
                    if (gr == gc) v += c8;
                    g_X1[e] = v;
                }
            }
        }
        GB32();
        {
            float qs[2][4] = {{c4, c5, c6, c7}, {c0, c1, c2, c3}};
            int sel = 1;
            for (int h = 0; h < 2; h++) {
                const float* T = (sel ? g_X1 : g_X0) + b * MSZ;
                float* Y       = (sel ? g_X0 : g_X1) + b * MSZ;
                float acc[2][2];
                mm32nb(T, g_B4 + b * MSZ, rB, cB, acc);
                int tx = t & 15, ty = t >> 4;
#pragma unroll
                for (int i = 0; i < 2; i++) {
                    int gr = rB + ty * 2 + i;
#pragma unroll
                    for (int j = 0; j < 2; j++) {
                        int gc = cB + tx * 2 + j;
                        int e = b * MSZ + gr * DIM + gc;
                        float v = acc[i][j] + qs[h][1] * __ldcg(&g_Bm[e]) +
                                  qs[h][2] * __ldcg(&g_B2[e]) + qs[h][3] * __ldcg(&g_B3[e]);
                        if (gr == gc) v += qs[h][0];
                        Y[gr * DIM + gc] = v;
                    }
                }
                sel ^= 1;
                GB32();
            }
            for (int sq = 0; sq < 5; sq++) {          // s = 5 squarings
                const float* X = (sel ? g_X1 : g_X0) + b * MSZ;
                float* Y       = (sel ? g_X0 : g_X1) + b * MSZ;
                float acc[2][2];
                mm32nb(X, X, rB, cB, acc);
                store32(Y, rB, cB, acc);
                sel ^= 1;
                GB32();
            }
        }
        // tail (result in X0): U[0]=I, U[1+b]=E^T, AW + B16[0..2]
        for (int i = cta * 256 + t; i < MSZ; i += 8192) {
            int r = i >> 7, c = i & 127;
            float v = (r == c) ? 1.0f : 0.0f;
            g_U[i] = v;
            img_put(g_B16, r, c, v);
        }
        for (int bm = 0; bm < 2; bm++) {
            const float* Em = g_X0 + bm * MSZ;
            for (int i = cta * 256 + t; i < MSZ; i += 8192) {
                int r = i >> 7, c = i & 127;
                float v = __ldcg(&Em[i]);
                g_U[(size_t)(1 + bm) * MSZ + c * DIM + r] = v;
                img_put(g_AW + (size_t)bm * 32768, c, r, v);
                img_put(g_B16 + (size_t)(1 + bm) * 32768, r, c, v);
            }
        }
        asm volatile("fence.proxy.async;" ::: "memory");
        GB32();   // 12th
        if (cta == 0 && t == 0) {
            flag_set(0, E);
            flag_set(1, E);
            flag_set(2, E);
        }
#undef GB32
    }

    // ================= CTA 32: order build (counting sort by pos&255) =========
    if (cta == 32) {
        __shared__ int hist[256], hbase[256];
        for (int i = t; i < 256; i += 512) hist[i] = 0;
        __syncthreads();
        for (int i = t; i < n; i += 512) atomicAdd(&hist[__ldg(&uniq[i]) & 255], 1);
        __syncthreads();
        if (t == 0) {
            int acc = 0;
            for (int r = 0; r < 256; r++) { hbase[r] = acc; acc += hist[r]; hist[r] = 0; }
        }
        __syncthreads();
        for (int i = t; i < n; i += 512) {
            int r = __ldg(&uniq[i]) & 255;
            int idx = hbase[r] + atomicAdd(&hist[r], 1);
            g_order[idx] = i;
        }
        __syncthreads();
        if (t == 0) {
            __threadfence();
            asm volatile("st.release.gpu.u32 [%0], %1;" :: "l"(&g_oflag), "r"(E) : "memory");
        }
    }
    __syncthreads();

    // ================= Phase B: doubling table tasks =================
    {
        const uint32_t AH = sb + HDR, BH = AH + 32768, AL = BH + 32768, BL = AL + 32768;
        int ph = 0;
        const int wid = t >> 5, lane = t & 31, wr = wid >> 2, wc = wid & 3;
        for (int task = cta; task < 508; task += NCTA) {
            int lvl, s;
            if (task < 4)        { lvl = 2; s = task; }
            else if (task < 12)  { lvl = 3; s = task - 4; }
            else if (task < 28)  { lvl = 4; s = task - 12; }
            else if (task < 60)  { lvl = 5; s = task - 28; }
            else if (task < 124) { lvl = 6; s = task - 60; }
            else if (task < 252) { lvl = 7; s = task - 124; }
            else                 { lvl = 8; s = task - 252; }
            int h = (lvl <= 3) ? 1 : (lvl == 4) ? 2 : 4;
            int ea = ((1 << h) - 1) + (s & ((1 << h) - 1));
            int eb = ((1 << (lvl - h)) - 1) + (s >> h);
            int e = ((1 << lvl) - 1) + s;
            if (t == 0) {
                flag_wait(ea, E);
                flag_wait(eb, E);
                const char* As =
                    (h == 1) ? (const char*)(g_AW  + (size_t)(s & 1)  * 32768)
                  : (h == 2) ? (const char*)(g_AT2 + (size_t)(s & 3)  * 32768)
                             : (const char*)(g_AT4 + (size_t)(s & 15) * 32768);
                const char* Bs = (const char*)(g_B16 + (size_t)eb * 32768);
                MBARRIER_EXPECT_TX(sb + 64, 65536);
                bulk_ld(AH, As, 32768, sb + 64);
                bulk_ld(BH, Bs, 32768, sb + 64);
                MBARRIER_EXPECT_TX(sb + 72, 65536);
                bulk_ld(AL, As + 32768, 32768, sb + 72);
                bulk_ld(BL, Bs + 32768, 32768, sb + 72);
            }
            float acc[2][4][4];
#pragma unroll
            for (int i = 0; i < 2; i++)
#pragma unroll
                for (int j = 0; j < 4; j++)
#pragma unroll
                    for (int kq = 0; kq < 4; kq++) acc[i][j][kq] = 0.0f;
            MBARRIER_WAIT_PARITY(sb + 64, ph);
            prodS(AH, BH, wr, wc, lane, acc);
            MBARRIER_WAIT_PARITY(sb + 72, ph);
            prodS(AH, BL, wr, wc, lane, acc);
            prodS(AL, BH, wr, wc, lane, acc);
            __syncthreads();
            float* Cs = (float*)(smem + HDR);
            store_fragS(Cs, wr, wc, lane, acc);
            __syncthreads();
            if (lvl < 8) {
                float* Ug = g_U + (size_t)e * MSZ;
                for (int i = t * 4; i < MSZ; i += 2048)
                    *(float4*)&Ug[i] = *(const float4*)&Cs[i];
                __half* dst = g_B16 + (size_t)e * 32768;
                for (int item = t; item < 2048; item += 512) {
                    int nn = item & 127, kb = item >> 7;
                    __half hv[8], lv[8];
#pragma unroll
                    for (int kk = 0; kk < 8; kk++) {
                        float v = Cs[(kb * 8 + kk) * DIM + nn];
                        __half hh = __float2half_rn(v);
                        hv[kk] = hh;
                        lv[kk] = __float2half_rn(v - __half2float(hh));
                    }
                    int k0 = kb * 8;
                    int idx = ((k0 >> 6) << 13) + (SW128(nn * 128 + (k0 & 63) * 2) >> 1);
                    *(uint4*)&dst[idx] = *(uint4*)hv;
                    *(uint4*)&dst[idx + 16384] = *(uint4*)lv;
                }
                if (lvl == 2 || lvl == 4) {
                    __half* dstA = (lvl == 2) ? g_AT2 + (size_t)s * 32768
                                              : g_AT4 + (size_t)s * 32768;
                    for (int item = t; item < 2048; item += 512) {
                        int kb = item & 15, m = item >> 4;
                        __half hv[8], lv[8];
#pragma unroll
                        for (int kk = 0; kk < 8; kk++) {
                            float v = Cs[m * DIM + kb * 8 + kk];
                            __half hh = __float2half_rn(v);
                            hv[kk] = hh;
                            lv[kk] = __float2half_rn(v - __half2float(hh));
                        }
                        int k0 = kb * 8;
                        int idx = ((k0 >> 6) << 13) + (SW128(m * 128 + (k0 & 63) * 2) >> 1);
                        *(uint4*)&dstA[idx] = *(uint4*)hv;
                        *(uint4*)&dstA[idx + 16384] = *(uint4*)lv;
                    }
                }
            } else {
                __half* dst = g_A16 + (size_t)s * 16384;
                for (int item = t; item < 2048; item += 512) {
                    int kb = item & 15, m = item >> 4;
                    __half hv[8];
#pragma unroll
                    for (int kk = 0; kk < 8; kk++)
                        hv[kk] = __float2half_rn(Cs[m * DIM + kb * 8 + kk]);
                    int k0 = kb * 8;
                    int idx = ((k0 >> 6) << 13) + (SW128(m * 128 + (k0 & 63) * 2) >> 1);
                    *(uint4*)&dst[idx] = *(uint4*)hv;
                }
            }
            __syncthreads();
            if (t == 0) {
                flag_set(e, E);
                done_add();
            }
            ph ^= 1;
        }
    }
    __syncthreads();

    // ================= Phase C: sorted, paired final =================
    if (t == 0) uflag_wait(&g_oflag, E);
    __syncthreads();

    int lo = (int)((long long)n * cta / NCTA);
    int hi = (int)((long long)n * (cta + 1) / NCTA);
    int m = hi - lo;

    int* s_pos = (int*)(smem + 128);
    int* s_ord = (int*)(smem + 384);
    int* u_i0  = (int*)(smem + 640);
    int* u_i1  = (int*)(smem + 896);
    int* u_r   = (int*)(smem + 1152);
    int* u_q0  = (int*)(smem + 1408);
    int* u_q1  = (int*)(smem + 1664);
    int* c_ci  = (int*)(smem + 1920);

    if (t < m) {
        int oi = g_order[lo + t];
        s_ord[t] = oi;
        s_pos[t] = __ldg(&uniq[oi]);
    }
    __syncthreads();
    if (t == 0) {
        int nu = 0, nc = 0, i = 0;
        while (i < m) {
            int pos = s_pos[i];
            if (pos < 256) { c_ci[nc++] = i; i++; continue; }
            int j = -1;
            if (i + 1 < m) {
                int p2 = s_pos[i + 1];
                if (p2 >= 256 && ((p2 ^ pos) & 255) == 0) j = i + 1;
            }
            u_i0[nu] = s_ord[i];
            u_i1[nu] = (j >= 0) ? s_ord[j] : -1;
            u_r[nu]  = pos & 255;
            u_q0[nu] = (pos >> 8) - 1;
            u_q1[nu] = (j >= 0) ? ((s_pos[j] >> 8) - 1) : ((pos >> 8) - 1);
            nu++;
            i += (j >= 0) ? 2 : 1;
        }
        s_cnt[0] = nu;
        s_cnt[1] = nc;
    }
    __syncthreads();
    const int nu = s_cnt[0], nc = s_cnt[1];
    int all = 0;

    // copies (rare: pos < 256)
    for (int k = 0; k < nc; k++) {
        int ci = c_ci[k];
        int e = s_pos[ci] - 1;
        if (t == 0) {
            if (!all) all = all_done(E);
            if (!all) flag_wait(e, E);
        }
        __syncthreads();
        const float* src = g_U + (size_t)e * MSZ;
        float* C = out + (size_t)s_ord[ci] * MSZ;
        for (int e2 = t * 4; e2 < MSZ; e2 += 2048) {
            float4 v = __ldcg((const float4*)&src[e2]);
            *(float4*)&C[e2] = v;
        }
    }

    // matmul units (2-slot ring, staged coalesced output, all-done fast path)
    if (t == 0) {
        if (!all) all = all_done(E);
        if (nu > 0) load_unit(sb, 0, u_r[0], u_q0[0], u_q1[0], E, all);
        if (nu > 1) {
            if (!all) all = all_done(E);
            load_unit(sb, 1, u_r[1], u_q0[1], u_q1[1], E, all);
        }
    }
    const int wid = t >> 5, lane = t & 31, wr = wid >> 2, wc = wid & 3;
    for (int u = 0; u < nu; u++) {
        int s = u & 1, rd = u >> 1;
        uint32_t basep = sb + HDR + (uint32_t)s * SLOT_SZ;
        float* stage = (float*)(smem + HDR + (size_t)s * SLOT_SZ);
        int pair = (u_i1[u] >= 0);
        float acc0[2][4][4], acc1[2][4][4];
#pragma unroll
        for (int a = 0; a < 2; a++)
#pragma unroll
            for (int bq = 0; bq < 4; bq++)
#pragma unroll
                for (int c = 0; c < 4; c++) { acc0[a][bq][c] = 0.0f; acc1[a][bq][c] = 0.0f; }

        MBARRIER_WAIT_PARITY(sb + s * 16, rd & 1);
        prodS2(basep, basep + 32768, basep + 65536, wr, wc, lane, pair, acc0, acc1);
        __syncthreads();                         // all warps done reading slot s
        stage_fragS(stage, wr, wc, lane, acc0);  // reuse slot s as padded stage
        __syncthreads();
        flushC(stage, out + (size_t)u_i0[u] * MSZ, t);
        if (pair) {
            __syncthreads();                     // stage reads done before rewrite
            stage_fragS(stage, wr, wc, lane, acc1);
            __syncthreads();
            flushC(stage, out + (size_t)u_i1[u] * MSZ, t);
        }
        MBARRIER_ARRIVE(sb + s * 16 + 8);        // slot free only after flush
        if (t == 0 && u + 2 < nu) {
            MBARRIER_WAIT_PARITY(sb + s * 16 + 8, rd & 1);
            if (!all) all = all_done(E);
            load_unit(sb, s, u_r[u + 2], u_q0[u + 2], u_q1[u + 2], E, all);
        }
    }
}

// ===========================================================================
extern "C" void kernel_launch(void* const* d_in, const int* in_sizes, int n_in,
                              void* d_out, int out_size) {
    const int* uniq = (const int*)d_in[0];
    const float* P  = (const float*)d_in[1];
    float* out = (float*)d_out;
    int n = in_sizes[0];

    k_epoch<<<1, 1>>>();
    cudaFuncSetAttribute(k_mega, cudaFuncAttributeMaxDynamicSharedMemorySize, MEGA_SMEM);
    k_mega<<<NCTA, 512, MEGA_SMEM>>>(uniq, P, out, n);
}

// round 16
// speedup vs baseline: 1.1813x; 1.1813x over previous
#include <cuda_runtime.h>
#include <cuda_fp16.h>
#include <cstdint>

#define DIM 128
#define MSZ (DIM * DIM)
#define NCTA 148

// fp32 tables for direct copies: g_U[e] = map for pos e+1, e in [0,254]
__device__ __align__(16) float g_U[255 * MSZ];
// fp16 images, chunked SW128 layout:
//  g_A16[s] : T_8[s] (pos 256+s), [m][k], HI ONLY (32KB)
//  g_B16[e] : entry e, [n][k], hi+lo (64KB)
//  g_AW[b]  : T_1[b] = W_b^T, [m][k], hi+lo
//  g_AT2[s] : T_2[s] [m][k] hi+lo ;  g_AT4[s] : T_4[s] [m][k] hi+lo
__device__ __align__(1024) __half g_A16[256 * 16384];
__device__ __align__(1024) __half g_B16[255 * 32768];
__device__ __align__(1024) __half g_AW[2 * 32768];
__device__ __align__(1024) __half g_AT2[4 * 32768];
__device__ __align__(1024) __half g_AT4[16 * 32768];
// expm scratch
__device__ __align__(16) float g_Bm[2 * MSZ];
__device__ __align__(16) float g_B2[2 * MSZ];
__device__ __align__(16) float g_B3[2 * MSZ];
__device__ __align__(16) float g_B4[2 * MSZ];
__device__ __align__(16) float g_X0[2 * MSZ];
__device__ __align__(16) float g_X1[2 * MSZ];
// dataflow state (monotonic across graph replays; epoch-tagged)
__device__ unsigned g_count = 0;
__device__ unsigned g_epoch = 0;
__device__ unsigned g_flag[511];
__device__ unsigned g_oflag = 0;
__device__ unsigned g_done = 0;        // completed phase-B tasks (508 per epoch)
__device__ int g_order[8192];

#define SW128(o) ((o) ^ (((o) >> 3) & 0x70))

// ------------------------------------------------------------- PTX helpers
__device__ __forceinline__ uint32_t smem_to_u32(const void* p) {
    uint32_t a;
    asm("{ .reg .u64 t; cvta.to.shared.u64 t, %1; cvt.u32.u64 %0, t; }" : "=r"(a) : "l"(p));
    return a;
}
#define MBARRIER_INIT(addr, cnt) \
    asm volatile("mbarrier.init.shared.b64 [%0], %1;" :: "r"((uint32_t)(addr)), "r"((uint32_t)(cnt)) : "memory")
#define MBARRIER_EXPECT_TX(addr, tx) \
    asm volatile("mbarrier.arrive.expect_tx.shared.b64 _, [%0], %1;" :: "r"((uint32_t)(addr)), "r"((uint32_t)(tx)) : "memory")
#define MBARRIER_ARRIVE(addr) \
    asm volatile("mbarrier.arrive.shared.b64 _, [%0];" :: "r"((uint32_t)(addr)) : "memory")
#define MBARRIER_WAIT_PARITY(mbar_smem_addr, phase_parity) do { \
    uint32_t _mbar = (uint32_t)(mbar_smem_addr); \
    uint32_t _parity = (uint32_t)(phase_parity); \
    uint32_t _done; \
    asm volatile("{\n\t.reg .pred p;\n\t" \
        "mbarrier.try_wait.parity.acquire.cta.shared::cta.b64 p, [%1], %2;\n\t" \
        "selp.b32 %0, 1, 0, p;\n\t}" : "=r"(_done) : "r"(_mbar), "r"(_parity) : "memory"); \
    if (!_done) { \
        asm volatile("{\n\t.reg .pred P1;\n\t" \
            "WAIT_LOOP_%=:\n\t" \
            "mbarrier.try_wait.parity.acquire.cta.shared::cta.b64 P1, [%0], %1, 0x989680;\n\t" \
            "@P1 bra.uni WAIT_DONE_%=;\n\t" \
            "bra.uni WAIT_LOOP_%=;\n\t" \
            "WAIT_DONE_%=:\n\t}" :: "r"(_mbar), "r"(_parity) : "memory"); \
    } \
} while (0)
__device__ __forceinline__ void bulk_ld(uint32_t dst, const void* src, uint32_t bytes, uint32_t mbar) {
    asm volatile("cp.async.bulk.shared::cta.global.mbarrier::complete_tx::bytes [%0], [%1], %2, [%3];"
                 :: "r"(dst), "l"(src), "r"(bytes), "r"(mbar) : "memory");
}
#define LDSM4(r0, r1, r2, r3, a) \
    asm volatile("ldmatrix.sync.aligned.m8n8.x4.shared.b16 {%0,%1,%2,%3}, [%4];" \
                 : "=r"(r0), "=r"(r1), "=r"(r2), "=r"(r3) : "r"(a))
#define MMA16816(c0, c1, c2, c3, a0, a1, a2, a3, b0, b1) \
    asm volatile("mma.sync.aligned.m16n8k16.row.col.f32.f16.f16.f32 " \
                 "{%0,%1,%2,%3}, {%4,%5,%6,%7}, {%8,%9}, {%0,%1,%2,%3};" \
                 : "+f"(c0), "+f"(c1), "+f"(c2), "+f"(c3) \
                 : "r"(a0), "r"(a1), "r"(a2), "r"(a3), "r"(b0), "r"(b1))

#define BAR_A() asm volatile("bar.sync 2, 256;" ::: "memory")

// hi/lo fp16 split write into a SW128 image
__device__ __forceinline__ void img_put(__half* img, int row, int k, float v) {
    int idx = ((k >> 6) << 13) + (SW128(row * 128 + (k & 63) * 2) >> 1);
    __half h = __float2half_rn(v);
    img[idx] = h;
    img[idx + 16384] = __float2half_rn(v - __half2float(h));
}

// --------------------------------------------- epoch-tagged ready flags
__device__ __forceinline__ void flag_set(int e, unsigned E) {
    asm volatile("fence.proxy.async;" ::: "memory");
    __threadfence();
    asm volatile("st.release.gpu.u32 [%0], %1;" :: "l"(&g_flag[e]), "r"(E) : "memory");
}
__device__ __forceinline__ void flag_wait(int e, unsigned E) {
    unsigned v;
    do {
        asm volatile("ld.acquire.gpu.u32 %0, [%1];" : "=r"(v) : "l"(&g_flag[e]) : "memory");
        if ((int)(v - E) >= 0) break;
        __nanosleep(32);
    } while (true);
}
__device__ __forceinline__ void uflag_wait(unsigned* p, unsigned E) {
    unsigned v;
    do {
        asm volatile("ld.acquire.gpu.u32 %0, [%1];" : "=r"(v) : "l"(p) : "memory");
        if ((int)(v - E) >= 0) break;
        __nanosleep(32);
    } while (true);
}
__device__ __forceinline__ void done_add() {
    unsigned one = 1;
    asm volatile("red.release.gpu.global.add.u32 [%0], %1;" :: "l"(&g_done), "r"(one) : "memory");
}
__device__ __forceinline__ int all_done(unsigned E) {
    unsigned v;
    asm volatile("ld.acquire.gpu.u32 %0, [%1];" : "=r"(v) : "l"(&g_done) : "memory");
    return (int)(v - 508u * E) >= 0;
}

// --------------------------------------- 32-CTA spin barrier (expm, t<256)
__device__ __forceinline__ void gbar32(unsigned target) {
    BAR_A();
    if (threadIdx.x == 0) {
        __threadfence();
        atomicAdd(&g_count, 1u);
        unsigned v;
        do {
            asm volatile("ld.acquire.gpu.u32 %0, [%1];" : "=r"(v) : "l"(&g_count) : "memory");
            if ((int)(v - target) >= 0) break;
            __nanosleep(32);
        } while (true);
    }
    BAR_A();
}

// --------------------- fp32 32x32 tile engine (named barrier, 256 threads)
__device__ __forceinline__ void mm32nb(const float* __restrict__ A, const float* __restrict__ B,
                                       int rowBase, int colBase, float acc[2][2]) {
    __shared__ __align__(16) float As[16][33];
    __shared__ __align__(16) float Bs[16][33];
    int t = threadIdx.x;
    int tx = t & 15, ty = t >> 4;
    acc[0][0] = acc[0][1] = acc[1][0] = acc[1][1] = 0.0f;
    for (int kc = 0; kc < DIM; kc += 16) {
        {
            int ar = t >> 3, ac = (t & 7) * 2;
            float2 av = __ldcg((const float2*)&A[(rowBase + ar) * DIM + kc + ac]);
            As[ac][ar] = av.x; As[ac + 1][ar] = av.y;
        }
        {
            int br = t >> 4, bc = (t & 15) * 2;
            float2 bv = __ldcg((const float2*)&B[(kc + br) * DIM + colBase + bc]);
            Bs[br][bc] = bv.x; Bs[br][bc + 1] = bv.y;
        }
        BAR_A();
#pragma unroll
        for (int kk = 0; kk < 16; kk++) {
            float a0 = As[kk][ty * 2], a1 = As[kk][ty * 2 + 1];
            float b0 = Bs[kk][tx * 2], b1 = Bs[kk][tx * 2 + 1];
            acc[0][0] += a0 * b0; acc[0][1] += a0 * b1;
            acc[1][0] += a1 * b0; acc[1][1] += a1 * b1;
        }
        BAR_A();
    }
}
// PS-fused variant (deg 12): A operand = c8 I + c9 B + c10 B2 + c11 B3 + c12 B4.
__device__ __forceinline__ void mm32ps(const float* __restrict__ Bm, const float* __restrict__ B2,
                                       const float* __restrict__ B3, const float* __restrict__ B4,
                                       int rowBase, int colBase, float acc[2][2]) {
    const float a0c = 2.48015873e-5f,  // 1/8!
                a1c = 2.75573192e-6f,  // 1/9!
                a2c = 2.75573192e-7f,  // 1/10!
                a3c = 2.50521084e-8f,  // 1/11!
                a4c = 2.08767570e-9f;  // 1/12!
    __shared__ __align__(16) float As[16][33];
    __shared__ __align__(16) float Bs[16][33];
    int t = threadIdx.x;
    int tx = t & 15, ty = t >> 4;
    acc[0][0] = acc[0][1] = acc[1][0] = acc[1][1] = 0.0f;
    for (int kc = 0; kc < DIM; kc += 16) {
        {
            int ar = t >> 3, ac = (t & 7) * 2;
            int row = rowBase + ar;
            int e = row * DIM + kc + ac;
            float2 v1 = __ldcg((const float2*)&Bm[e]);
            float2 v2 = __ldcg((const float2*)&B2[e]);
            float2 v3 = __ldcg((const float2*)&B3[e]);
            float2 v4 = __ldcg((const float2*)&B4[e]);
            float vx = a1c * v1.x + a2c * v2.x + a3c * v3.x + a4c * v4.x;
            float vy = a1c * v1.y + a2c * v2.y + a3c * v3.y + a4c * v4.y;
            if (row == kc + ac) vx += a0c;
            if (row == kc + ac + 1) vy += a0c;
            As[ac][ar] = vx; As[ac + 1][ar] = vy;
        }
        {
            int br = t >> 4, bc = (t & 15) * 2;
            float2 bv = __ldcg((const float2*)&B4[(kc + br) * DIM + colBase + bc]);
            Bs[br][bc] = bv.x; Bs[br][bc + 1] = bv.y;
        }
        BAR_A();
#pragma unroll
        for (int kk = 0; kk < 16; kk++) {
            float a0 = As[kk][ty * 2], a1 = As[kk][ty * 2 + 1];
            float b0 = Bs[kk][tx * 2], b1 = Bs[kk][tx * 2 + 1];
            acc[0][0] += a0 * b0; acc[0][1] += a0 * b1;
            acc[1][0] += a1 * b0; acc[1][1] += a1 * b1;
        }
        BAR_A();
    }
}
__device__ __forceinline__ void store32(float* __restrict__ C, int rowBase, int colBase,
                                        float acc[2][2]) {
    int tx = threadIdx.x & 15, ty = threadIdx.x >> 4;
#pragma unroll
    for (int i = 0; i < 2; i++)
#pragma unroll
        for (int j = 0; j < 2; j++)
            C[(rowBase + ty * 2 + i) * DIM + colBase + tx * 2 + j] = acc[i][j];
}

// ---------------------------------------------------------------------------
// prodS: warp tile 32x32 single product (wr 0..3, wc 0..3), 16 warps.
// ---------------------------------------------------------------------------
__device__ __forceinline__ void prodS(uint32_t aimg, uint32_t bimg,
                                      int wr, int wc, int lane, float acc[2][4][4]) {
    int rA = (wr * 32 + (lane & 15)) * 128;
    int seg = (lane >> 4) * 16;
    int rB = (wc * 32 + (lane & 15)) * 128;
#pragma unroll
    for (int ks = 0; ks < 8; ks++) {
        uint32_t coff = (uint32_t)(ks >> 2) * 16384u;
        int kw2 = (ks & 3) * 32;
        uint32_t a0[4], a1[4], b0[4], b1[4];
        LDSM4(a0[0], a0[1], a0[2], a0[3], aimg + coff + (uint32_t)SW128(rA + kw2 + seg));
        LDSM4(a1[0], a1[1], a1[2], a1[3], aimg + coff + (uint32_t)SW128(rA + 2048 + kw2 + seg));
        LDSM4(b0[0], b0[1], b0[2], b0[3], bimg + coff + (uint32_t)SW128(rB + kw2 + seg));
        LDSM4(b1[0], b1[1], b1[2], b1[3], bimg + coff + (uint32_t)SW128(rB + 2048 + kw2 + seg));
        MMA16816(acc[0][0][0], acc[0][0][1], acc[0][0][2], acc[0][0][3],
                 a0[0], a0[1], a0[2], a0[3], b0[0], b0[2]);
        MMA16816(acc[0][1][0], acc[0][1][1], acc[0][1][2], acc[0][1][3],
                 a0[0], a0[1], a0[2], a0[3], b0[1], b0[3]);
        MMA16816(acc[0][2][0], acc[0][2][1], acc[0][2][2], acc[0][2][3],
                 a0[0], a0[1], a0[2], a0[3], b1[0], b1[2]);
        MMA16816(acc[0][3][0], acc[0][3][1], acc[0][3][2], acc[0][3][3],
                 a0[0], a0[1], a0[2], a0[3], b1[1], b1[3]);
        MMA16816(acc[1][0][0], acc[1][0][1], acc[1][0][2], acc[1][0][3],
                 a1[0], a1[1], a1[2], a1[3], b0[0], b0[2]);
        MMA16816(acc[1][1][0], acc[1][1][1], acc[1][1][2], acc[1][1][3],
                 a1[0], a1[1], a1[2], a1[3], b0[1], b0[3]);
        MMA16816(acc[1][2][0], acc[1][2][1], acc[1][2][2], acc[1][2][3],
                 a1[0], a1[1], a1[2], a1[3], b1[0], b1[2]);
        MMA16816(acc[1][3][0], acc[1][3][1], acc[1][3][2], acc[1][3][3],
                 a1[0], a1[1], a1[2], a1[3], b1[1], b1[3]);
    }
}
// paired: A fragments shared across two B images (two positions, same A)
__device__ __forceinline__ void prodS2(uint32_t aimg, uint32_t b0img, uint32_t b1img,
                                       int wr, int wc, int lane, int pair,
                                       float acc0[2][4][4], float acc1[2][4][4]) {
    int rA = (wr * 32 + (lane & 15)) * 128;
    int seg = (lane >> 4) * 16;
    int rB = (wc * 32 + (lane & 15)) * 128;
#pragma unroll
    for (int ks = 0; ks < 8; ks++) {
        uint32_t coff = (uint32_t)(ks >> 2) * 16384u;
        int kw2 = (ks & 3) * 32;
        uint32_t bo0 = coff + (uint32_t)SW128(rB + kw2 + seg);
        uint32_t bo1 = coff + (uint32_t)SW128(rB + 2048 + kw2 + seg);
        uint32_t a0[4], a1[4], b0[4], b1[4];
        LDSM4(a0[0], a0[1], a0[2], a0[3], aimg + coff + (uint32_t)SW128(rA + kw2 + seg));
        LDSM4(a1[0], a1[1], a1[2], a1[3], aimg + coff + (uint32_t)SW128(rA + 2048 + kw2 + seg));
        LDSM4(b0[0], b0[1], b0[2], b0[3], b0img + bo0);
        LDSM4(b1[0], b1[1], b1[2], b1[3], b0img + bo1);
        MMA16816(acc0[0][0][0], acc0[0][0][1], acc0[0][0][2], acc0[0][0][3],
                 a0[0], a0[1], a0[2], a0[3], b0[0], b0[2]);
        MMA16816(acc0[0][1][0], acc0[0][1][1], acc0[0][1][2], acc0[0][1][3],
                 a0[0], a0[1], a0[2], a0[3], b0[1], b0[3]);
        MMA16816(acc0[0][2][0], acc0[0][2][1], acc0[0][2][2], acc0[0][2][3],
                 a0[0], a0[1], a0[2], a0[3], b1[0], b1[2]);
        MMA16816(acc0[0][3][0], acc0[0][3][1], acc0[0][3][2], acc0[0][3][3],
                 a0[0], a0[1], a0[2], a0[3], b1[1], b1[3]);
        MMA16816(acc0[1][0][0], acc0[1][0][1], acc0[1][0][2], acc0[1][0][3],
                 a1[0], a1[1], a1[2], a1[3], b0[0], b0[2]);
        MMA16816(acc0[1][1][0], acc0[1][1][1], acc0[1][1][2], acc0[1][1][3],
                 a1[0], a1[1], a1[2], a1[3], b0[1], b0[3]);
        MMA16816(acc0[1][2][0], acc0[1][2][1], acc0[1][2][2], acc0[1][2][3],
                 a1[0], a1[1], a1[2], a1[3], b1[0], b1[2]);
        MMA16816(acc0[1][3][0], acc0[1][3][1], acc0[1][3][2], acc0[1][3][3],
                 a1[0], a1[1], a1[2], a1[3], b1[1], b1[3]);
        if (pair) {
            LDSM4(b0[0], b0[1], b0[2], b0[3], b1img + bo0);
            LDSM4(b1[0], b1[1], b1[2], b1[3], b1img + bo1);
            MMA16816(acc1[0][0][0], acc1[0][0][1], acc1[0][0][2], acc1[0][0][3],
                     a0[0], a0[1], a0[2], a0[3], b0[0], b0[2]);
            MMA16816(acc1[0][1][0], acc1[0][1][1], acc1[0][1][2], acc1[0][1][3],
                     a0[0], a0[1], a0[2], a0[3], b0[1], b0[3]);
            MMA16816(acc1[0][2][0], acc1[0][2][1], acc1[0][2][2], acc1[0][2][3],
                     a0[0], a0[1], a0[2], a0[3], b1[0], b1[2]);
            MMA16816(acc1[0][3][0], acc1[0][3][1], acc1[0][3][2], acc1[0][3][3],
                     a0[0], a0[1], a0[2], a0[3], b1[1], b1[3]);
            MMA16816(acc1[1][0][0], acc1[1][0][1], acc1[1][0][2], acc1[1][0][3],
                     a1[0], a1[1], a1[2], a1[3], b0[0], b0[2]);
            MMA16816(acc1[1][1][0], acc1[1][1][1], acc1[1][1][2], acc1[1][1][3],
                     a1[0], a1[1], a1[2], a1[3], b0[1], b0[3]);
            MMA16816(acc1[1][2][0], acc1[1][2][1], acc1[1][2][2], acc1[1][2][3],
                     a1[0], a1[1], a1[2], a1[3], b1[0], b1[2]);
            MMA16816(acc1[1][3][0], acc1[1][3][1], acc1[1][3][2], acc1[1][3][3],
                     a1[0], a1[1], a1[2], a1[3], b1[1], b1[3]);
        }
    }
}
__device__ __forceinline__ void store_fragS(float* __restrict__ C, int wr, int wc, int lane,
                                            float acc[2][4][4]) {
#pragma unroll
    for (int at = 0; at < 2; at++) {
        int row0 = wr * 32 + at * 16 + (lane >> 2);
#pragma unroll
        for (int ct = 0; ct < 4; ct++) {
            int col = wc * 32 + ct * 8 + (lane & 3) * 2;
            *(float2*)&C[row0 * DIM + col]       = make_float2(acc[at][ct][0], acc[at][ct][1]);
            *(float2*)&C[(row0 + 8) * DIM + col] = make_float2(acc[at][ct][2], acc[at][ct][3]);
        }
    }
}

__global__ void k_epoch() { atomicAdd(&g_epoch, 1u); }

// ===========================================================================
// k_mega: ONE dataflow kernel, 512 threads.
//   Phase A (CTAs 0-31, t<256): expm (s=5, PS deg 12 fused-init, 5 squarings).
//   CTA 32: counting-sort positions by (pos & 255) -> g_order.
//   Phase B (all CTAs): 508 doubling tasks, gated by parent flags; g_done++.
//   Phase C: sorted chunks, paired A-reuse HMMA (R14 structure).
// ===========================================================================
#define NBARE 11u
#define HDR 3072
#define SLOT_SZ 98304
#define MEGA_SMEM (HDR + 2 * SLOT_SZ)

__device__ __forceinline__ void load_unit(uint32_t sb, int slot, int rr, int q0, int q1,
                                          int pair, unsigned E, int skip) {
    if (!skip) {
        flag_wait(255 + rr, E);
        flag_wait(q0, E);
        if (q1 != q0) flag_wait(q1, E);
    }
    uint32_t mb = sb + (uint32_t)slot * 16;
    uint32_t dst = sb + HDR + (uint32_t)slot * SLOT_SZ;
    if (pair) {
        MBARRIER_EXPECT_TX(mb, 98304);
        bulk_ld(dst,         g_A16 + (size_t)rr * 16384, 32768, mb);
        bulk_ld(dst + 32768, g_B16 + (size_t)q0 * 32768, 32768, mb);
        bulk_ld(dst + 65536, g_B16 + (size_t)q1 * 32768, 32768, mb);
    } else {
        MBARRIER_EXPECT_TX(mb, 65536);
        bulk_ld(dst,         g_A16 + (size_t)rr * 16384, 32768, mb);
        bulk_ld(dst + 32768, g_B16 + (size_t)q0 * 32768, 32768, mb);
    }
}

__global__ void __launch_bounds__(512, 1) k_mega(const int* __restrict__ uniq,
                                                 const float* __restrict__ P,
                                                 float* __restrict__ out, int n) {
    extern __shared__ char smem[];
    uint32_t sb = smem_to_u32(smem);
    const int t = threadIdx.x;
    const int cta = blockIdx.x;
    __shared__ unsigned sE;
    __shared__ int s_cnt[2];
    if (t == 0) {
#pragma unroll
        for (int s = 0; s < 2; s++) {
            MBARRIER_INIT(sb + s * 16, 1);        // slot full
            MBARRIER_INIT(sb + s * 16 + 8, 512);  // slot empty
        }
        MBARRIER_INIT(sb + 64, 1);                // phase-B hi
        MBARRIER_INIT(sb + 72, 1);                // phase-B lo
        sE = *(volatile unsigned*)&g_epoch;
    }
    __syncthreads();
    const unsigned E = sE;

    // ================= Phase A: expm (CTAs 0-31, threads < 256) =================
    if (cta < 32 && t < 256) {
        const unsigned baseE = (E - 1u) * NBARE * 32u;
        int barId = 0;
#define GB32() gbar32(baseE + (unsigned)(++barId) * 32u)
        const float c0 = 1.0f, c1 = 1.0f, c2 = 0.5f, c3 = 1.0f / 6.0f, c4 = 1.0f / 24.0f;
        const float c5 = 1.0f / 120.0f, c6 = 1.0f / 720.0f, c7 = 1.0f / 5040.0f;

        const int b = cta >> 4, tile = cta & 15;
        const int rB = (tile >> 2) * 32, cB = (tile & 3) * 32;

        for (int idx = cta * 256 + t; idx < 2 * MSZ; idx += 8192) {
            int bb = idx >> 14, r = (idx >> 7) & 127, c = idx & 127;
            float h = __ldg(&P[bb * MSZ + r * DIM + c]) - __ldg(&P[bb * MSZ + c * DIM + r]);
            g_Bm[idx] = h * (1.0f / 32.0f);          // s = 5
        }
        GB32();
        {
            float acc[2][2];
            mm32nb(g_Bm + b * MSZ, g_Bm + b * MSZ, rB, cB, acc);
            store32(g_B2 + b * MSZ, rB, cB, acc);
        }
        GB32();
        {
            float acc[2][2];
            mm32nb(g_B2 + b * MSZ, g_Bm + b * MSZ, rB, cB, acc);
            store32(g_B3 + b * MSZ, rB, cB, acc);
            float acc2[2][2];
            mm32nb(g_B2 + b * MSZ, g_B2 + b * MSZ, rB, cB, acc2);
            store32(g_B4 + b * MSZ, rB, cB, acc2);
        }
        GB32();
        {   // deg-12 top chunk fused into the A-operand load: result -> X1
            float acc[2][2];
            mm32ps(g_Bm + b * MSZ, g_B2 + b * MSZ, g_B3 + b * MSZ, g_B4 + b * MSZ,
                   rB, cB, acc);
            int tx = t & 15, ty = t >> 4;
#pragma unroll
            for (int i = 0; i < 2; i++) {
                int gr = rB + ty * 2 + i;
#pragma unroll
                for (int j = 0; j < 2; j++) {
                    int gc = cB + tx * 2 + j;
                    int e = b * MSZ + gr * DIM + gc;
                    float v = acc[i][j] + c5 * __ldcg(&g_Bm[e]) +
                              c6 * __ldcg(&g_B2[e]) + c7 * __ldcg(&g_B3[e]);
                    if (gr == gc) v += c4;
                    g_X1[e] = v;
                }
            }
        }
        GB32();
        {
            // single remaining Horner: Y = T*B4 + (c0 I + c1 B + c2 B2 + c3 B3)
            {
                const float* T = g_X1 + b * MSZ;
                float* Y       = g_X0 + b * MSZ;
                float acc[2][2];
                mm32nb(T, g_B4 + b * MSZ, rB, cB, acc);
                int tx = t & 15, ty = t >> 4;
#pragma unroll
                for (int i = 0; i < 2; i++) {
                    int gr = rB + ty * 2 + i;
#pragma unroll
                    for (int j = 0; j < 2; j++) {
                        int gc = cB + tx * 2 + j;
                        int e = b * MSZ + gr * DIM + gc;
                        float v = acc[i][j] + c1 * __ldcg(&g_Bm[e]) +
                                  c2 * __ldcg(&g_B2[e]) + c3 * __ldcg(&g_B3[e]);
                        if (gr == gc) v += c0;
                        Y[gr * DIM + gc] = v;
                    }
                }
            }
            GB32();
            int sel = 0;                              // result in X0
            for (int sq = 0; sq < 5; sq++) {          // s = 5 squarings
                const float* X = (sel ? g_X1 : g_X0) + b * MSZ;
                float* Y       = (sel ? g_X0 : g_X1) + b * MSZ;
                float acc[2][2];
                mm32nb(X, X, rB, cB, acc);
                store32(Y, rB, cB, acc);
                sel ^= 1;
                GB32();
            }
            // after 5 squarings: result in X1
        }
        // tail (result in X1): U[0]=I, U[1+b]=E^T, AW + B16[0..2]
        for (int i = cta * 256 + t; i < MSZ; i += 8192) {
            int r = i >> 7, c = i & 127;
            float v = (r == c) ? 1.0f : 0.0f;
            g_U[i] = v;
            img_put(g_B16, r, c, v);
        }
        for (int bm = 0; bm < 2; bm++) {
            const float* Em = g_X1 + bm * MSZ;
            for (int i = cta * 256 + t; i < MSZ; i += 8192) {
                int r = i >> 7, c = i & 127;
                float v = __ldcg(&Em[i]);
                g_U[(size_t)(1 + bm) * MSZ + c * DIM + r] = v;
                img_put(g_AW + (size_t)bm * 32768, c, r, v);
                img_put(g_B16 + (size_t)(1 + bm) * 32768, r, c, v);
            }
        }
        asm volatile("fence.proxy.async;" ::: "memory");
        GB32();   // 11th
        if (cta == 0 && t == 0) {
            flag_set(0, E);
            flag_set(1, E);
            flag_set(2, E);
        }
#undef GB32
    }

    // ================= CTA 32: order build (counting sort by pos&255) =========
    if (cta == 32) {
        __shared__ int hist[256], hbase[256];
        for (int i = t; i < 256; i += 512) hist[i] = 0;
        __syncthreads();
        for (int i = t; i < n; i += 512) atomicAdd(&hist[__ldg(&uniq[i]) & 255], 1);
        __syncthreads();
        if (t == 0) {
            int acc = 0;
            for (int r = 0; r < 256; r++) { hbase[r] = acc; acc += hist[r]; hist[r] = 0; }
        }
        __syncthreads();
        for (int i = t; i < n; i += 512) {
            int r = __ldg(&uniq[i]) & 255;
            int idx = hbase[r] + atomicAdd(&hist[r], 1);
            g_order[idx] = i;
        }
        __syncthreads();
        if (t == 0) {
            __threadfence();
            asm volatile("st.release.gpu.u32 [%0], %1;" :: "l"(&g_oflag), "r"(E) : "memory");
        }
    }
    __syncthreads();

    // ================= Phase B: doubling table tasks =================
    {
        const uint32_t AH = sb + HDR, BH = AH + 32768, AL = BH + 32768, BL = AL + 32768;
        int ph = 0;
        const int wid = t >> 5, lane = t & 31, wr = wid >> 2, wc = wid & 3;
        for (int task = cta; task < 508; task += NCTA) {
            int lvl, s;
            if (task < 4)        { lvl = 2; s = task; }
            else if (task < 12)  { lvl = 3; s = task - 4; }
            else if (task < 28)  { lvl = 4; s = task - 12; }
            else if (task < 60)  { lvl = 5; s = task - 28; }
            else if (task < 124) { lvl = 6; s = task - 60; }
            else if (task < 252) { lvl = 7; s = task - 124; }
            else                 { lvl = 8; s = task - 252; }
            int h = (lvl <= 3) ? 1 : (lvl == 4) ? 2 : 4;
            int ea = ((1 << h) - 1) + (s & ((1 << h) - 1));
            int eb = ((1 << (lvl - h)) - 1) + (s >> h);
            int e = ((1 << lvl) - 1) + s;
            if (t == 0) {
                flag_wait(ea, E);
                flag_wait(eb, E);
                const char* As =
                    (h == 1) ? (const char*)(g_AW  + (size_t)(s & 1)  * 32768)
                  : (h == 2) ? (const char*)(g_AT2 + (size_t)(s & 3)  * 32768)
                             : (const char*)(g_AT4 + (size_t)(s & 15) * 32768);
                const char* Bs = (const char*)(g_B16 + (size_t)eb * 32768);
                MBARRIER_EXPECT_TX(sb + 64, 65536);
                bulk_ld(AH, As, 32768, sb + 64);
                bulk_ld(BH, Bs, 32768, sb + 64);
                MBARRIER_EXPECT_TX(sb + 72, 65536);
                bulk_ld(AL, As + 32768, 32768, sb + 72);
                bulk_ld(BL, Bs + 32768, 32768, sb + 72);
            }
            float acc[2][4][4];
#pragma unroll
            for (int i = 0; i < 2; i++)
#pragma unroll
                for (int j = 0; j < 4; j++)
#pragma unroll
                    for (int kq = 0; kq < 4; kq++) acc[i][j][kq] = 0.0f;
            MBARRIER_WAIT_PARITY(sb + 64, ph);
            prodS(AH, BH, wr, wc, lane, acc);
            MBARRIER_WAIT_PARITY(sb + 72, ph);
            prodS(AH, BL, wr, wc, lane, acc);
            prodS(AL, BH, wr, wc, lane, acc);
            __syncthreads();
            float* Cs = (float*)(smem + HDR);
            store_fragS(Cs, wr, wc, lane, acc);
            __syncthreads();
            if (lvl < 8) {
                float* Ug = g_U + (size_t)e * MSZ;
                for (int i = t * 4; i < MSZ; i += 2048)
                    *(float4*)&Ug[i] = *(const float4*)&Cs[i];
                __half* dst = g_B16 + (size_t)e * 32768;
                for (int item = t; item < 2048; item += 512) {
                    int nn = item & 127, kb = item >> 7;
                    __half hv[8], lv[8];
#pragma unroll
                    for (int kk = 0; kk < 8; kk++) {
                        float v = Cs[(kb * 8 + kk) * DIM + nn];
                        __half hh = __float2half_rn(v);
                        hv[kk] = hh;
                        lv[kk] = __float2half_rn(v - __half2float(hh));
                    }
                    int k0 = kb * 8;
                    int idx = ((k0 >> 6) << 13) + (SW128(nn * 128 + (k0 & 63) * 2) >> 1);
                    *(uint4*)&dst[idx] = *(uint4*)hv;
                    *(uint4*)&dst[idx + 16384] = *(uint4*)lv;
                }
                if (lvl == 2 || lvl == 4) {
                    __half* dstA = (lvl == 2) ? g_AT2 + (size_t)s * 32768
                                              : g_AT4 + (size_t)s * 32768;
                    for (int item = t; item < 2048; item += 512) {
                        int kb = item & 15, m = item >> 4;
                        __half hv[8], lv[8];
#pragma unroll
                        for (int kk = 0; kk < 8; kk++) {
                            float v = Cs[m * DIM + kb * 8 + kk];
                            __half hh = __float2half_rn(v);
                            hv[kk] = hh;
                            lv[kk] = __float2half_rn(v - __half2float(hh));
                        }
                        int k0 = kb * 8;
                        int idx = ((k0 >> 6) << 13) + (SW128(m * 128 + (k0 & 63) * 2) >> 1);
                        *(uint4*)&dstA[idx] = *(uint4*)hv;
                        *(uint4*)&dstA[idx + 16384] = *(uint4*)lv;
                    }
                }
            } else {
                __half* dst = g_A16 + (size_t)s * 16384;
                for (int item = t; item < 2048; item += 512) {
                    int kb = item & 15, m = item >> 4;
                    __half hv[8];
#pragma unroll
                    for (int kk = 0; kk < 8; kk++)
                        hv[kk] = __float2half_rn(Cs[m * DIM + kb * 8 + kk]);
                    int k0 = kb * 8;
                    int idx = ((k0 >> 6) << 13) + (SW128(m * 128 + (k0 & 63) * 2) >> 1);
                    *(uint4*)&dst[idx] = *(uint4*)hv;
                }
            }
            __syncthreads();
            if (t == 0) {
                flag_set(e, E);
                done_add();
            }
            ph ^= 1;
        }
    }
    __syncthreads();

    // ================= Phase C: sorted, paired final (R14 structure) ==========
    if (t == 0) uflag_wait(&g_oflag, E);
    __syncthreads();

    int lo = (int)((long long)n * cta / NCTA);
    int hi = (int)((long long)n * (cta + 1) / NCTA);
    int m = hi - lo;

    int* s_pos = (int*)(smem + 128);
    int* s_ord = (int*)(smem + 384);
    int* u_i0  = (int*)(smem + 640);
    int* u_i1  = (int*)(smem + 896);
    int* u_r   = (int*)(smem + 1152);
    int* u_q0  = (int*)(smem + 1408);
    int* u_q1  = (int*)(smem + 1664);
    int* c_ci  = (int*)(smem + 1920);

    if (t < m) {
        int oi = g_order[lo + t];
        s_ord[t] = oi;
        s_pos[t] = __ldg(&uniq[oi]);
    }
    __syncthreads();
    if (t == 0) {
        int nu = 0, nc = 0, i = 0;
        while (i < m) {
            int pos = s_pos[i];
            if (pos < 256) { c_ci[nc++] = i; i++; continue; }
            int j = -1;
            if (i + 1 < m) {
                int p2 = s_pos[i + 1];
                if (p2 >= 256 && ((p2 ^ pos) & 255) == 0) j = i + 1;
            }
            u_i0[nu] = s_ord[i];
            u_i1[nu] = (j >= 0) ? s_ord[j] : -1;
            u_r[nu]  = pos & 255;
            u_q0[nu] = (pos >> 8) - 1;
            u_q1[nu] = (j >= 0) ? ((s_pos[j] >> 8) - 1) : ((pos >> 8) - 1);
            nu++;
            i += (j >= 0) ? 2 : 1;
        }
        s_cnt[0] = nu;
        s_cnt[1] = nc;
    }
    __syncthreads();
    const int nu = s_cnt[0], nc = s_cnt[1];
    int all = 0;

    // copies (rare: pos < 256)
    for (int k = 0; k < nc; k++) {
        int ci = c_ci[k];
        int e = s_pos[ci] - 1;
        if (t == 0) {
            if (!all) all = all_done(E);
            if (!all) flag_wait(e, E);
        }
        __syncthreads();
        const float* src = g_U + (size_t)e * MSZ;
        float* C = out + (size_t)s_ord[ci] * MSZ;
        for (int e2 = t * 4; e2 < MSZ; e2 += 2048) {
            float4 v = __ldcg((const float4*)&src[e2]);
            *(float4*)&C[e2] = v;
        }
    }

    // matmul units (2-slot ring, t0-inline prefetch, all-done fast path)
    if (t == 0) {
        if (!all) all = all_done(E);
        if (nu > 0) load_unit(sb, 0, u_r[0], u_q0[0], u_q1[0], u_i1[0] >= 0, E, all);
        if (nu > 1) {
            if (!all) all = all_done(E);
            load_unit(sb, 1, u_r[1], u_q0[1], u_q1[1], u_i1[1] >= 0, E, all);
        }
    }
    const int wid = t >> 5, lane = t & 31, wr = wid >> 2, wc = wid & 3;
    for (int u = 0; u < nu; u++) {
        int s = u & 1, rd = u >> 1;
        uint32_t basep = sb + HDR + (uint32_t)s * SLOT_SZ;
        int pair = (u_i1[u] >= 0);
        float acc0[2][4][4], acc1[2][4][4];
#pragma unroll
        for (int a = 0; a < 2; a++)
#pragma unroll
            for (int bq = 0; bq < 4; bq++)
#pragma unroll
                for (int c = 0; c < 4; c++) { acc0[a][bq][c] = 0.0f; acc1[a][bq][c] = 0.0f; }

        MBARRIER_WAIT_PARITY(sb + s * 16, rd & 1);
        prodS2(basep, basep + 32768, basep + 65536, wr, wc, lane, pair, acc0, acc1);
        MBARRIER_ARRIVE(sb + s * 16 + 8);
        if (t == 0 && u + 2 < nu) {
            MBARRIER_WAIT_PARITY(sb + s * 16 + 8, rd & 1);
            if (!all) all = all_done(E);
            load_unit(sb, s, u_r[u + 2], u_q0[u + 2], u_q1[u + 2], u_i1[u + 2] >= 0, E, all);
        }
        store_fragS(out + (size_t)u_i0[u] * MSZ, wr, wc, lane, acc0);
        if (pair) store_fragS(out + (size_t)u_i1[u] * MSZ, wr, wc, lane, acc1);
    }
}

// ===========================================================================
extern "C" void kernel_launch(void* const* d_in, const int* in_sizes, int n_in,
                              void* d_out, int out_size) {
    const int* uniq = (const int*)d_in[0];
    const float* P  = (const float*)d_in[1];
    float* out = (float*)d_out;
    int n = in_sizes[0];

    k_epoch<<<1, 1>>>();
    cudaFuncSetAttribute(k_mega, cudaFuncAttributeMaxDynamicSharedMemorySize, MEGA_SMEM);
    k_mega<<<NCTA, 512, MEGA_SMEM>>>(uniq, P, out, n);
}

// round 17
// speedup vs baseline: 1.2122x; 1.0262x over previous
#include <cuda_runtime.h>
#include <cuda_fp16.h>
#include <cstdint>

#define DIM 128
#define MSZ (DIM * DIM)
#define NCTA 148

// fp32 tables for direct copies: g_U[e] = map for pos e+1, e in [0,254]
__device__ __align__(16) float g_U[255 * MSZ];
// fp16 images, chunked SW128 layout:
//  g_A16[s] : T_8[s] (pos 256+s), [m][k], HI ONLY (32KB)
//  g_B16[e] : entry e, [n][k]: hi always; lo only for levels 1..4 (e<=30)
//  g_AW[b]  : T_1[b] = W_b^T, [m][k], hi+lo
//  g_AT2[s] : T_2[s] [m][k] hi+lo ;  g_AT4[s] : T_4[s] [m][k] hi+lo
__device__ __align__(1024) __half g_A16[256 * 16384];
__device__ __align__(1024) __half g_B16[255 * 32768];
__device__ __align__(1024) __half g_AW[2 * 32768];
__device__ __align__(1024) __half g_AT2[4 * 32768];
__device__ __align__(1024) __half g_AT4[16 * 32768];
// expm scratch
__device__ __align__(16) float g_Bm[2 * MSZ];
__device__ __align__(16) float g_B2[2 * MSZ];
__device__ __align__(16) float g_B3[2 * MSZ];
__device__ __align__(16) float g_B4[2 * MSZ];
__device__ __align__(16) float g_X0[2 * MSZ];
__device__ __align__(16) float g_X1[2 * MSZ];
// dataflow state (monotonic across graph replays; epoch-tagged)
__device__ unsigned g_count = 0;
__device__ unsigned g_epoch = 0;
__device__ unsigned g_flag[511];
__device__ unsigned g_oflag = 0;
__device__ unsigned g_done = 0;        // completed phase-B tasks (508 per epoch)
__device__ int g_order[8192];

#define SW128(o) ((o) ^ (((o) >> 3) & 0x70))

// ------------------------------------------------------------- PTX helpers
__device__ __forceinline__ uint32_t smem_to_u32(const void* p) {
    uint32_t a;
    asm("{ .reg .u64 t; cvta.to.shared.u64 t, %1; cvt.u32.u64 %0, t; }" : "=r"(a) : "l"(p));
    return a;
}
#define MBARRIER_INIT(addr, cnt) \
    asm volatile("mbarrier.init.shared.b64 [%0], %1;" :: "r"((uint32_t)(addr)), "r"((uint32_t)(cnt)) : "memory")
#define MBARRIER_EXPECT_TX(addr, tx) \
    asm volatile("mbarrier.arrive.expect_tx.shared.b64 _, [%0], %1;" :: "r"((uint32_t)(addr)), "r"((uint32_t)(tx)) : "memory")
#define MBARRIER_ARRIVE(addr) \
    asm volatile("mbarrier.arrive.shared.b64 _, [%0];" :: "r"((uint32_t)(addr)) : "memory")
#define MBARRIER_WAIT_PARITY(mbar_smem_addr, phase_parity) do { \
    uint32_t _mbar = (uint32_t)(mbar_smem_addr); \
    uint32_t _parity = (uint32_t)(phase_parity); \
    uint32_t _done; \
    asm volatile("{\n\t.reg .pred p;\n\t" \
        "mbarrier.try_wait.parity.acquire.cta.shared::cta.b64 p, [%1], %2;\n\t" \
        "selp.b32 %0, 1, 0, p;\n\t}" : "=r"(_done) : "r"(_mbar), "r"(_parity) : "memory"); \
    if (!_done) { \
        asm volatile("{\n\t.reg .pred P1;\n\t" \
            "WAIT_LOOP_%=:\n\t" \
            "mbarrier.try_wait.parity.acquire.cta.shared::cta.b64 P1, [%0], %1, 0x989680;\n\t" \
            "@P1 bra.uni WAIT_DONE_%=;\n\t" \
            "bra.uni WAIT_LOOP_%=;\n\t" \
            "WAIT_DONE_%=:\n\t}" :: "r"(_mbar), "r"(_parity) : "memory"); \
    } \
} while (0)
__device__ __forceinline__ void bulk_ld(uint32_t dst, const void* src, uint32_t bytes, uint32_t mbar) {
    asm volatile("cp.async.bulk.shared::cta.global.mbarrier::complete_tx::bytes [%0], [%1], %2, [%3];"
                 :: "r"(dst), "l"(src), "r"(bytes), "r"(mbar) : "memory");
}
#define LDSM4(r0, r1, r2, r3, a) \
    asm volatile("ldmatrix.sync.aligned.m8n8.x4.shared.b16 {%0,%1,%2,%3}, [%4];" \
                 : "=r"(r0), "=r"(r1), "=r"(r2), "=r"(r3) : "r"(a))
#define MMA16816(c0, c1, c2, c3, a0, a1, a2, a3, b0, b1) \
    asm volatile("mma.sync.aligned.m16n8k16.row.col.f32.f16.f16.f32 " \
                 "{%0,%1,%2,%3}, {%4,%5,%6,%7}, {%8,%9}, {%0,%1,%2,%3};" \
                 : "+f"(c0), "+f"(c1), "+f"(c2), "+f"(c3) \
                 : "r"(a0), "r"(a1), "r"(a2), "r"(a3), "r"(b0), "r"(b1))

#define BAR_A() asm volatile("bar.sync 2, 256;" ::: "memory")

// hi/lo fp16 split write into a SW128 image
__device__ __forceinline__ void img_put(__half* img, int row, int k, float v) {
    int idx = ((k >> 6) << 13) + (SW128(row * 128 + (k & 63) * 2) >> 1);
    __half h = __float2half_rn(v);
    img[idx] = h;
    img[idx + 16384] = __float2half_rn(v - __half2float(h));
}

// --------------------------------------------- epoch-tagged ready flags
__device__ __forceinline__ void flag_set(int e, unsigned E) {
    asm volatile("fence.proxy.async;" ::: "memory");
    __threadfence();
    asm volatile("st.release.gpu.u32 [%0], %1;" :: "l"(&g_flag[e]), "r"(E) : "memory");
}
__device__ __forceinline__ void flag_wait(int e, unsigned E) {
    unsigned v;
    do {
        asm volatile("ld.acquire.gpu.u32 %0, [%1];" : "=r"(v) : "l"(&g_flag[e]) : "memory");
        if ((int)(v - E) >= 0) break;
        __nanosleep(32);
    } while (true);
}
__device__ __forceinline__ int flag_try(int e, unsigned E) {
    unsigned v;
    asm volatile("ld.acquire.gpu.u32 %0, [%1];" : "=r"(v) : "l"(&g_flag[e]) : "memory");
    return (int)(v - E) >= 0;
}
__device__ __forceinline__ void uflag_wait(unsigned* p, unsigned E) {
    unsigned v;
    do {
        asm volatile("ld.acquire.gpu.u32 %0, [%1];" : "=r"(v) : "l"(p) : "memory");
        if ((int)(v - E) >= 0) break;
        __nanosleep(32);
    } while (true);
}
__device__ __forceinline__ void done_add() {
    unsigned one = 1;
    asm volatile("red.release.gpu.global.add.u32 [%0], %1;" :: "l"(&g_done), "r"(one) : "memory");
}
__device__ __forceinline__ int all_done(unsigned E) {
    unsigned v;
    asm volatile("ld.acquire.gpu.u32 %0, [%1];" : "=r"(v) : "l"(&g_done) : "memory");
    return (int)(v - 508u * E) >= 0;
}

// --------------------------------------- 32-CTA spin barrier (expm, t<256)
__device__ __forceinline__ void gbar32(unsigned target) {
    BAR_A();
    if (threadIdx.x == 0) {
        __threadfence();
        atomicAdd(&g_count, 1u);
        unsigned v;
        do {
            asm volatile("ld.acquire.gpu.u32 %0, [%1];" : "=r"(v) : "l"(&g_count) : "memory");
            if ((int)(v - target) >= 0) break;
            __nanosleep(32);
        } while (true);
    }
    BAR_A();
}

// --------------------- fp32 32x32 tile engine (named barrier, 256 threads)
__device__ __forceinline__ void mm32nb(const float* __restrict__ A, const float* __restrict__ B,
                                       int rowBase, int colBase, float acc[2][2]) {
    __shared__ __align__(16) float As[16][33];
    __shared__ __align__(16) float Bs[16][33];
    int t = threadIdx.x;
    int tx = t & 15, ty = t >> 4;
    acc[0][0] = acc[0][1] = acc[1][0] = acc[1][1] = 0.0f;
    for (int kc = 0; kc < DIM; kc += 16) {
        {
            int ar = t >> 3, ac = (t & 7) * 2;
            float2 av = __ldcg((const float2*)&A[(rowBase + ar) * DIM + kc + ac]);
            As[ac][ar] = av.x; As[ac + 1][ar] = av.y;
        }
        {
            int br = t >> 4, bc = (t & 15) * 2;
            float2 bv = __ldcg((const float2*)&B[(kc + br) * DIM + colBase + bc]);
            Bs[br][bc] = bv.x; Bs[br][bc + 1] = bv.y;
        }
        BAR_A();
#pragma unroll
        for (int kk = 0; kk < 16; kk++) {
            float a0 = As[kk][ty * 2], a1 = As[kk][ty * 2 + 1];
            float b0 = Bs[kk][tx * 2], b1 = Bs[kk][tx * 2 + 1];
            acc[0][0] += a0 * b0; acc[0][1] += a0 * b1;
            acc[1][0] += a1 * b0; acc[1][1] += a1 * b1;
        }
        BAR_A();
    }
}
// PS-fused variant (deg 12): A operand = c8 I + c9 B + c10 B2 + c11 B3 + c12 B4.
__device__ __forceinline__ void mm32ps(const float* __restrict__ Bm, const float* __restrict__ B2,
                                       const float* __restrict__ B3, const float* __restrict__ B4,
                                       int rowBase, int colBase, float acc[2][2]) {
    const float a0c = 2.48015873e-5f, a1c = 2.75573192e-6f, a2c = 2.75573192e-7f,
                a3c = 2.50521084e-8f, a4c = 2.08767570e-9f;
    __shared__ __align__(16) float As[16][33];
    __shared__ __align__(16) float Bs[16][33];
    int t = threadIdx.x;
    int tx = t & 15, ty = t >> 4;
    acc[0][0] = acc[0][1] = acc[1][0] = acc[1][1] = 0.0f;
    for (int kc = 0; kc < DIM; kc += 16) {
        {
            int ar = t >> 3, ac = (t & 7) * 2;
            int row = rowBase + ar;
            int e = row * DIM + kc + ac;
            float2 v1 = __ldcg((const float2*)&Bm[e]);
            float2 v2 = __ldcg((const float2*)&B2[e]);
            float2 v3 = __ldcg((const float2*)&B3[e]);
            float2 v4 = __ldcg((const float2*)&B4[e]);
            float vx = a1c * v1.x + a2c * v2.x + a3c * v3.x + a4c * v4.x;
            float vy = a1c * v1.y + a2c * v2.y + a3c * v3.y + a4c * v4.y;
            if (row == kc + ac) vx += a0c;
            if (row == kc + ac + 1) vy += a0c;
            As[ac][ar] = vx; As[ac + 1][ar] = vy;
        }
        {
            int br = t >> 4, bc = (t & 15) * 2;
            float2 bv = __ldcg((const float2*)&B4[(kc + br) * DIM + colBase + bc]);
            Bs[br][bc] = bv.x; Bs[br][bc + 1] = bv.y;
        }
        BAR_A();
#pragma unroll
        for (int kk = 0; kk < 16; kk++) {
            float a0 = As[kk][ty * 2], a1 = As[kk][ty * 2 + 1];
            float b0 = Bs[kk][tx * 2], b1 = Bs[kk][tx * 2 + 1];
            acc[0][0] += a0 * b0; acc[0][1] += a0 * b1;
            acc[1][0] += a1 * b0; acc[1][1] += a1 * b1;
        }
        BAR_A();
    }
}
__device__ __forceinline__ void store32(float* __restrict__ C, int rowBase, int colBase,
                                        float acc[2][2]) {
    int tx = threadIdx.x & 15, ty = threadIdx.x >> 4;
#pragma unroll
    for (int i = 0; i < 2; i++)
#pragma unroll
        for (int j = 0; j < 2; j++)
            C[(rowBase + ty * 2 + i) * DIM + colBase + tx * 2 + j] = acc[i][j];
}

// ---------------------------------------------------------------------------
// prodS: warp tile 32x32 single product (wr 0..3, wc 0..3), 16 warps.
// ---------------------------------------------------------------------------
__device__ __forceinline__ void prodS(uint32_t aimg, uint32_t bimg,
                                      int wr, int wc, int lane, float acc[2][4][4]) {
    int rA = (wr * 32 + (lane & 15)) * 128;
    int seg = (lane >> 4) * 16;
    int rB = (wc * 32 + (lane & 15)) * 128;
#pragma unroll
    for (int ks = 0; ks < 8; ks++) {
        uint32_t coff = (uint32_t)(ks >> 2) * 16384u;
        int kw2 = (ks & 3) * 32;
        uint32_t a0[4], a1[4], b0[4], b1[4];
        LDSM4(a0[0], a0[1], a0[2], a0[3], aimg + coff + (uint32_t)SW128(rA + kw2 + seg));
        LDSM4(a1[0], a1[1], a1[2], a1[3], aimg + coff + (uint32_t)SW128(rA + 2048 + kw2 + seg));
        LDSM4(b0[0], b0[1], b0[2], b0[3], bimg + coff + (uint32_t)SW128(rB + kw2 + seg));
        LDSM4(b1[0], b1[1], b1[2], b1[3], bimg + coff + (uint32_t)SW128(rB + 2048 + kw2 + seg));
        MMA16816(acc[0][0][0], acc[0][0][1], acc[0][0][2], acc[0][0][3],
                 a0[0], a0[1], a0[2], a0[3], b0[0], b0[2]);
        MMA16816(acc[0][1][0], acc[0][1][1], acc[0][1][2], acc[0][1][3],
                 a0[0], a0[1], a0[2], a0[3], b0[1], b0[3]);
        MMA16816(acc[0][2][0], acc[0][2][1], acc[0][2][2], acc[0][2][3],
                 a0[0], a0[1], a0[2], a0[3], b1[0], b1[2]);
        MMA16816(acc[0][3][0], acc[0][3][1], acc[0][3][2], acc[0][3][3],
                 a0[0], a0[1], a0[2], a0[3], b1[1], b1[3]);
        MMA16816(acc[1][0][0], acc[1][0][1], acc[1][0][2], acc[1][0][3],
                 a1[0], a1[1], a1[2], a1[3], b0[0], b0[2]);
        MMA16816(acc[1][1][0], acc[1][1][1], acc[1][1][2], acc[1][1][3],
                 a1[0], a1[1], a1[2], a1[3], b0[1], b0[3]);
        MMA16816(acc[1][2][0], acc[1][2][1], acc[1][2][2], acc[1][2][3],
                 a1[0], a1[1], a1[2], a1[3], b1[0], b1[2]);
        MMA16816(acc[1][3][0], acc[1][3][1], acc[1][3][2], acc[1][3][3],
                 a1[0], a1[1], a1[2], a1[3], b1[1], b1[3]);
    }
}
// paired: A fragments shared across two B images (two positions, same A)
__device__ __forceinline__ void prodS2(uint32_t aimg, uint32_t b0img, uint32_t b1img,
                                       int wr, int wc, int lane, int pair,
                                       float acc0[2][4][4], float acc1[2][4][4]) {
    int rA = (wr * 32 + (lane & 15)) * 128;
    int seg = (lane >> 4) * 16;
    int rB = (wc * 32 + (lane & 15)) * 128;
#pragma unroll
    for (int ks = 0; ks < 8; ks++) {
        uint32_t coff = (uint32_t)(ks >> 2) * 16384u;
        int kw2 = (ks & 3) * 32;
        uint32_t bo0 = coff + (uint32_t)SW128(rB + kw2 + seg);
        uint32_t bo1 = coff + (uint32_t)SW128(rB + 2048 + kw2 + seg);
        uint32_t a0[4], a1[4], b0[4], b1[4];
        LDSM4(a0[0], a0[1], a0[2], a0[3], aimg + coff + (uint32_t)SW128(rA + kw2 + seg));
        LDSM4(a1[0], a1[1], a1[2], a1[3], aimg + coff + (uint32_t)SW128(rA + 2048 + kw2 + seg));
        LDSM4(b0[0], b0[1], b0[2], b0[3], b0img + bo0);
        LDSM4(b1[0], b1[1], b1[2], b1[3], b0img + bo1);
        MMA16816(acc0[0][0][0], acc0[0][0][1], acc0[0][0][2], acc0[0][0][3],
                 a0[0], a0[1], a0[2], a0[3], b0[0], b0[2]);
        MMA16816(acc0[0][1][0], acc0[0][1][1], acc0[0][1][2], acc0[0][1][3],
                 a0[0], a0[1], a0[2], a0[3], b0[1], b0[3]);
        MMA16816(acc0[0][2][0], acc0[0][2][1], acc0[0][2][2], acc0[0][2][3],
                 a0[0], a0[1], a0[2], a0[3], b1[0], b1[2]);
        MMA16816(acc0[0][3][0], acc0[0][3][1], acc0[0][3][2], acc0[0][3][3],
                 a0[0], a0[1], a0[2], a0[3], b1[1], b1[3]);
        MMA16816(acc0[1][0][0], acc0[1][0][1], acc0[1][0][2], acc0[1][0][3],
                 a1[0], a1[1], a1[2], a1[3], b0[0], b0[2]);
        MMA16816(acc0[1][1][0], acc0[1][1][1], acc0[1][1][2], acc0[1][1][3],
                 a1[0], a1[1], a1[2], a1[3], b0[1], b0[3]);
        MMA16816(acc0[1][2][0], acc0[1][2][1], acc0[1][2][2], acc0[1][2][3],
                 a1[0], a1[1], a1[2], a1[3], b1[0], b1[2]);
        MMA16816(acc0[1][3][0], acc0[1][3][1], acc0[1][3][2], acc0[1][3][3],
                 a1[0], a1[1], a1[2], a1[3], b1[1], b1[3]);
        if (pair) {
            LDSM4(b0[0], b0[1], b0[2], b0[3], b1img + bo0);
            LDSM4(b1[0], b1[1], b1[2], b1[3], b1img + bo1);
            MMA16816(acc1[0][0][0], acc1[0][0][1], acc1[0][0][2], acc1[0][0][3],
                     a0[0], a0[1], a0[2], a0[3], b0[0], b0[2]);
            MMA16816(acc1[0][1][0], acc1[0][1][1], acc1[0][1][2], acc1[0][1][3],
                     a0[0], a0[1], a0[2], a0[3], b0[1], b0[3]);
            MMA16816(acc1[0][2][0], acc1[0][2][1], acc1[0][2][2], acc1[0][2][3],
                     a0[0], a0[1], a0[2], a0[3], b1[0], b1[2]);
            MMA16816(acc1[0][3][0], acc1[0][3][1], acc1[0][3][2], acc1[0][3][3],
                     a0[0], a0[1], a0[2], a0[3], b1[1], b1[3]);
            MMA16816(acc1[1][0][0], acc1[1][0][1], acc1[1][0][2], acc1[1][0][3],
                     a1[0], a1[1], a1[2], a1[3], b0[0], b0[2]);
            MMA16816(acc1[1][1][0], acc1[1][1][1], acc1[1][1][2], acc1[1][1][3],
                     a1[0], a1[1], a1[2], a1[3], b0[1], b0[3]);
            MMA16816(acc1[1][2][0], acc1[1][2][1], acc1[1][2][2], acc1[1][2][3],
                     a1[0], a1[1], a1[2], a1[3], b1[0], b1[2]);
            MMA16816(acc1[1][3][0], acc1[1][3][1], acc1[1][3][2], acc1[1][3][3],
                     a1[0], a1[1], a1[2], a1[3], b1[1], b1[3]);
        }
    }
}
__device__ __forceinline__ void store_fragS(float* __restrict__ C, int wr, int wc, int lane,
                                            float acc[2][4][4]) {
#pragma unroll
    for (int at = 0; at < 2; at++) {
        int row0 = wr * 32 + at * 16 + (lane >> 2);
#pragma unroll
        for (int ct = 0; ct < 4; ct++) {
            int col = wc * 32 + ct * 8 + (lane & 3) * 2;
            *(float2*)&C[row0 * DIM + col]       = make_float2(acc[at][ct][0], acc[at][ct][1]);
            *(float2*)&C[(row0 + 8) * DIM + col] = make_float2(acc[at][ct][2], acc[at][ct][3]);
        }
    }
}

__global__ void k_epoch() { atomicAdd(&g_epoch, 1u); }

// ===========================================================================
// k_mega: ONE dataflow kernel, 512 threads.
//   Phase A (CTAs 0-31, t<256): expm (s=5, PS deg 12 fused-init, 5 squarings).
//   CTA 32: counting-sort positions by (pos & 255) -> g_order.
//   Phase B (all CTAs): 508 doubling tasks, opportunistic next-task prefetch
//     overlapping the epilogue; lo-split skipped for levels 5-7 (dead data).
//   Phase C: sorted chunks, paired A-reuse HMMA (R14 structure).
// ===========================================================================
#define NBARE 11u
#define HDR 3072
#define SLOT_SZ 98304
#define MEGA_SMEM (HDR + 2 * SLOT_SZ)

// task index -> level/slot/parents/operand pointers
__device__ __forceinline__ void task_info(int task, int& lvl, int& s, int& ea, int& eb,
                                          int& e, const char*& As, const char*& Bs) {
    if (task < 4)        { lvl = 2; s = task; }
    else if (task < 12)  { lvl = 3; s = task - 4; }
    else if (task < 28)  { lvl = 4; s = task - 12; }
    else if (task < 60)  { lvl = 5; s = task - 28; }
    else if (task < 124) { lvl = 6; s = task - 60; }
    else if (task < 252) { lvl = 7; s = task - 124; }
    else                 { lvl = 8; s = task - 252; }
    int h = (lvl <= 3) ? 1 : (lvl == 4) ? 2 : 4;
    ea = ((1 << h) - 1) + (s & ((1 << h) - 1));
    eb = ((1 << (lvl - h)) - 1) + (s >> h);
    e = ((1 << lvl) - 1) + s;
    As = (h == 1) ? (const char*)(g_AW  + (size_t)(s & 1)  * 32768)
       : (h == 2) ? (const char*)(g_AT2 + (size_t)(s & 3)  * 32768)
                  : (const char*)(g_AT4 + (size_t)(s & 15) * 32768);
    Bs = (const char*)(g_B16 + (size_t)eb * 32768);
}
__device__ __forceinline__ void loadB_task(uint32_t sb, const char* As, const char* Bs) {
    uint32_t AH = sb + HDR, BH = AH + 32768, AL = BH + 32768, BL = AL + 32768;
    MBARRIER_EXPECT_TX(sb + 64, 65536);
    bulk_ld(AH, As, 32768, sb + 64);
    bulk_ld(BH, Bs, 32768, sb + 64);
    MBARRIER_EXPECT_TX(sb + 72, 65536);
    bulk_ld(AL, As + 32768, 32768, sb + 72);
    bulk_ld(BL, Bs + 32768, 32768, sb + 72);
}

__device__ __forceinline__ void load_unit(uint32_t sb, int slot, int rr, int q0, int q1,
                                          int pair, unsigned E, int skip) {
    if (!skip) {
        flag_wait(255 + rr, E);
        flag_wait(q0, E);
        if (q1 != q0) flag_wait(q1, E);
    }
    uint32_t mb = sb + (uint32_t)slot * 16;
    uint32_t dst = sb + HDR + (uint32_t)slot * SLOT_SZ;
    if (pair) {
        MBARRIER_EXPECT_TX(mb, 98304);
        bulk_ld(dst,         g_A16 + (size_t)rr * 16384, 32768, mb);
        bulk_ld(dst + 32768, g_B16 + (size_t)q0 * 32768, 32768, mb);
        bulk_ld(dst + 65536, g_B16 + (size_t)q1 * 32768, 32768, mb);
    } else {
        MBARRIER_EXPECT_TX(mb, 65536);
        bulk_ld(dst,         g_A16 + (size_t)rr * 16384, 32768, mb);
        bulk_ld(dst + 32768, g_B16 + (size_t)q0 * 32768, 32768, mb);
    }
}

__global__ void __launch_bounds__(512, 1) k_mega(const int* __restrict__ uniq,
                                                 const float* __restrict__ P,
                                                 float* __restrict__ out, int n) {
    extern __shared__ char smem[];
    uint32_t sb = smem_to_u32(smem);
    const int t = threadIdx.x;
    const int cta = blockIdx.x;
    __shared__ unsigned sE;
    __shared__ int s_cnt[2];
    __shared__ int s_pre;
    if (t == 0) {
#pragma unroll
        for (int s = 0; s < 2; s++) {
            MBARRIER_INIT(sb + s * 16, 1);        // slot full
            MBARRIER_INIT(sb + s * 16 + 8, 512);  // slot empty
        }
        MBARRIER_INIT(sb + 64, 1);                // phase-B hi
        MBARRIER_INIT(sb + 72, 1);                // phase-B lo
        sE = *(volatile unsigned*)&g_epoch;
    }
    __syncthreads();
    const unsigned E = sE;

    // ================= Phase A: expm (CTAs 0-31, threads < 256) =================
    if (cta < 32 && t < 256) {
        const unsigned baseE = (E - 1u) * NBARE * 32u;
        int barId = 0;
#define GB32() gbar32(baseE + (unsigned)(++barId) * 32u)
        const float c0 = 1.0f, c1 = 1.0f, c2 = 0.5f, c3 = 1.0f / 6.0f, c4 = 1.0f / 24.0f;
        const float c5 = 1.0f / 120.0f, c6 = 1.0f / 720.0f, c7 = 1.0f / 5040.0f;

        const int b = cta >> 4, tile = cta & 15;
        const int rB = (tile >> 2) * 32, cB = (tile & 3) * 32;

        for (int idx = cta * 256 + t; idx < 2 * MSZ; idx += 8192) {
            int bb = idx >> 14, r = (idx >> 7) & 127, c = idx & 127;
            float h = __ldg(&P[bb * MSZ + r * DIM + c]) - __ldg(&P[bb * MSZ + c * DIM + r]);
            g_Bm[idx] = h * (1.0f / 32.0f);          // s = 5
        }
        GB32();
        {
            float acc[2][2];
            mm32nb(g_Bm + b * MSZ, g_Bm + b * MSZ, rB, cB, acc);
            store32(g_B2 + b * MSZ, rB, cB, acc);
        }
        GB32();
        {
            float acc[2][2];
            mm32nb(g_B2 + b * MSZ, g_Bm + b * MSZ, rB, cB, acc);
            store32(g_B3 + b * MSZ, rB, cB, acc);
            float acc2[2][2];
            mm32nb(g_B2 + b * MSZ, g_B2 + b * MSZ, rB, cB, acc2);
            store32(g_B4 + b * MSZ, rB, cB, acc2);
        }
        GB32();
        {   // deg-12 top chunk fused into the A-operand load: result -> X1
            float acc[2][2];
            mm32ps(g_Bm + b * MSZ, g_B2 + b * MSZ, g_B3 + b * MSZ, g_B4 + b * MSZ,
                   rB, cB, acc);
            int tx = t & 15, ty = t >> 4;
#pragma unroll
            for (int i = 0; i < 2; i++) {
                int gr = rB + ty * 2 + i;
#pragma unroll
                for (int j = 0; j < 2; j++) {
                    int gc = cB + tx * 2 + j;
                    int e = b * MSZ + gr * DIM + gc;
                    float v = acc[i][j] + c5 * __ldcg(&g_Bm[e]) +
                              c6 * __ldcg(&g_B2[e]) + c7 * __ldcg(&g_B3[e]);
                    if (gr == gc) v += c4;
                    g_X1[e] = v;
                }
            }
        }
        GB32();
        {
            {   // single remaining Horner: Y = T*B4 + (c0 I + c1 B + c2 B2 + c3 B3)
                const float* T = g_X1 + b * MSZ;
                float* Y       = g_X0 + b * MSZ;
                float acc[2][2];
                mm32nb(T, g_B4 + b * MSZ, rB, cB, acc);
                int tx = t & 15, ty = t >> 4;
#pragma unroll
                for (int i = 0; i < 2; i++) {
                    int gr = rB + ty * 2 + i;
#pragma unroll
                    for (int j = 0; j < 2; j++) {
                        int gc = cB + tx * 2 + j;
                        int e = b * MSZ + gr * DIM + gc;
                        float v = acc[i][j] + c1 * __ldcg(&g_Bm[e]) +
                                  c2 * __ldcg(&g_B2[e]) + c3 * __ldcg(&g_B3[e]);
                        if (gr == gc) v += c0;
                        Y[gr * DIM + gc] = v;
                    }
                }
            }
            GB32();
            int sel = 0;                              // result in X0
            for (int sq = 0; sq < 5; sq++) {          // s = 5 squarings
                const float* X = (sel ? g_X1 : g_X0) + b * MSZ;
                float* Y       = (sel ? g_X0 : g_X1) + b * MSZ;
                float acc[2][2];
                mm32nb(X, X, rB, cB, acc);
                store32(Y, rB, cB, acc);
                sel ^= 1;
                GB32();
            }
            // after 5 squarings: result in X1
        }
        // tail (result in X1): U[0]=I, U[1+b]=E^T, AW + B16[0..2]
        for (int i = cta * 256 + t; i < MSZ; i += 8192) {
            int r = i >> 7, c = i & 127;
            float v = (r == c) ? 1.0f : 0.0f;
            g_U[i] = v;
            img_put(g_B16, r, c, v);
        }
        for (int bm = 0; bm < 2; bm++) {
            const float* Em = g_X1 + bm * MSZ;
            for (int i = cta * 256 + t; i < MSZ; i += 8192) {
                int r = i >> 7, c = i & 127;
                float v = __ldcg(&Em[i]);
                g_U[(size_t)(1 + bm) * MSZ + c * DIM + r] = v;
                img_put(g_AW + (size_t)bm * 32768, c, r, v);
                img_put(g_B16 + (size_t)(1 + bm) * 32768, r, c, v);
            }
        }
        asm volatile("fence.proxy.async;" ::: "memory");
        GB32();   // 11th
        if (cta == 0 && t == 0) {
            flag_set(0, E);
            flag_set(1, E);
            flag_set(2, E);
        }
#undef GB32
    }

    // ================= CTA 32: order build (counting sort by pos&255) =========
    if (cta == 32) {
        __shared__ int hist[256], hbase[256];
        for (int i = t; i < 256; i += 512) hist[i] = 0;
        __syncthreads();
        for (int i = t; i < n; i += 512) atomicAdd(&hist[__ldg(&uniq[i]) & 255], 1);
        __syncthreads();
        if (t == 0) {
            int acc = 0;
            for (int r = 0; r < 256; r++) { hbase[r] = acc; acc += hist[r]; hist[r] = 0; }
        }
        __syncthreads();
        for (int i = t; i < n; i += 512) {
            int r = __ldg(&uniq[i]) & 255;
            int idx = hbase[r] + atomicAdd(&hist[r], 1);
            g_order[idx] = i;
        }
        __syncthreads();
        if (t == 0) {
            __threadfence();
            asm volatile("st.release.gpu.u32 [%0], %1;" :: "l"(&g_oflag), "r"(E) : "memory");
        }
    }
    __syncthreads();

    // ================= Phase B: doubling table tasks (prefetched) =============
    {
        const uint32_t AH = sb + HDR, BH = AH + 32768, AL = BH + 32768, BL = AL + 32768;
        float* Cs = (float*)(smem + HDR + 131072);   // separate 64KB result stage
        int ph = 0;
        int pre = 0;
        const int wid = t >> 5, lane = t & 31, wr = wid >> 2, wc = wid & 3;
        for (int task = cta; task < 508; task += NCTA) {
            int lvl, s, ea, eb, e;
            const char *As, *Bs;
            task_info(task, lvl, s, ea, eb, e, As, Bs);
            if (t == 0 && !pre) {
                flag_wait(ea, E);
                flag_wait(eb, E);
                loadB_task(sb, As, Bs);
            }
            float acc[2][4][4];
#pragma unroll
            for (int i = 0; i < 2; i++)
#pragma unroll
                for (int j = 0; j < 4; j++)
#pragma unroll
                    for (int kq = 0; kq < 4; kq++) acc[i][j][kq] = 0.0f;
            MBARRIER_WAIT_PARITY(sb + 64, ph);
            prodS(AH, BH, wr, wc, lane, acc);
            MBARRIER_WAIT_PARITY(sb + 72, ph);
            prodS(AH, BL, wr, wc, lane, acc);
            prodS(AL, BH, wr, wc, lane, acc);
            __syncthreads();   // all warps done reading images
            // opportunistic prefetch of next task (never blocks -> deadlock-free)
            if (t == 0) {
                int ok = 0;
                int ntask = task + NCTA;
                if (ntask < 508) {
                    int nl, ns, nea, neb, ne;
                    const char *nAs, *nBs;
                    task_info(ntask, nl, ns, nea, neb, ne, nAs, nBs);
                    if (flag_try(nea, E) && flag_try(neb, E)) {
                        loadB_task(sb, nAs, nBs);
                        ok = 1;
                    }
                }
                s_pre = ok;
            }
            store_fragS(Cs, wr, wc, lane, acc);
            __syncthreads();
            if (lvl < 8) {
                float* Ug = g_U + (size_t)e * MSZ;
                for (int i = t * 4; i < MSZ; i += 2048)
                    *(float4*)&Ug[i] = *(const float4*)&Cs[i];
                __half* dst = g_B16 + (size_t)e * 32768;
                int wantLo = (lvl <= 4);   // lo halves dead for levels 5-7
                for (int item = t; item < 2048; item += 512) {
                    int nn = item & 127, kb = item >> 7;
                    __half hv[8], lv[8];
#pragma unroll
                    for (int kk = 0; kk < 8; kk++) {
                        float v = Cs[(kb * 8 + kk) * DIM + nn];
                        __half hh = __float2half_rn(v);
                        hv[kk] = hh;
                        lv[kk] = __float2half_rn(v - __half2float(hh));
                    }
                    int k0 = kb * 8;
                    int idx = ((k0 >> 6) << 13) + (SW128(nn * 128 + (k0 & 63) * 2) >> 1);
                    *(uint4*)&dst[idx] = *(uint4*)hv;
                    if (wantLo) *(uint4*)&dst[idx + 16384] = *(uint4*)lv;
                }
                if (lvl == 2 || lvl == 4) {
                    __half* dstA = (lvl == 2) ? g_AT2 + (size_t)s * 32768
                                              : g_AT4 + (size_t)s * 32768;
                    for (int item = t; item < 2048; item += 512) {
                        int kb = item & 15, m = item >> 4;
                        __half hv[8], lv[8];
#pragma unroll
                        for (int kk = 0; kk < 8; kk++) {
                            float v = Cs[m * DIM + kb * 8 + kk];
                            __half hh = __float2half_rn(v);
                            hv[kk] = hh;
                            lv[kk] = __float2half_rn(v - __half2float(hh));
                        }
                        int k0 = kb * 8;
                        int idx = ((k0 >> 6) << 13) + (SW128(m * 128 + (k0 & 63) * 2) >> 1);
                        *(uint4*)&dstA[idx] = *(uint4*)hv;
                        *(uint4*)&dstA[idx + 16384] = *(uint4*)lv;
                    }
                }
            } else {
                __half* dst = g_A16 + (size_t)s * 16384;
                for (int item = t; item < 2048; item += 512) {
                    int kb = item & 15, m = item >> 4;
                    __half hv[8];
#pragma unroll
                    for (int kk = 0; kk < 8; kk++)
                        hv[kk] = __float2half_rn(Cs[m * DIM + kb * 8 + kk]);
                    int k0 = kb * 8;
                    int idx = ((k0 >> 6) << 13) + (SW128(m * 128 + (k0 & 63) * 2) >> 1);
                    *(uint4*)&dst[idx] = *(uint4*)hv;
                }
            }
            __syncthreads();
            if (t == 0) {
                flag_set(e, E);
                done_add();
            }
            pre = s_pre;
            ph ^= 1;
        }
    }
    __syncthreads();

    // ================= Phase C: sorted, paired final (R14 structure) ==========
    if (t == 0) uflag_wait(&g_oflag, E);
    __syncthreads();

    int lo = (int)((long long)n * cta / NCTA);
    int hi = (int)((long long)n * (cta + 1) / NCTA);
    int m = hi - lo;

    int* s_pos = (int*)(smem + 128);
    int* s_ord = (int*)(smem + 384);
    int* u_i0  = (int*)(smem + 640);
    int* u_i1  = (int*)(smem + 896);
    int* u_r   = (int*)(smem + 1152);
    int* u_q0  = (int*)(smem + 1408);
    int* u_q1  = (int*)(smem + 1664);
    int* c_ci  = (int*)(smem + 1920);

    if (t < m) {
        int oi = g_order[lo + t];
        s_ord[t] = oi;
        s_pos[t] = __ldg(&uniq[oi]);
    }
    __syncthreads();
    if (t == 0) {
        int nu = 0, nc = 0, i = 0;
        while (i < m) {
            int pos = s_pos[i];
            if (pos < 256) { c_ci[nc++] = i; i++; continue; }
            int j = -1;
            if (i + 1 < m) {
                int p2 = s_pos[i + 1];
                if (p2 >= 256 && ((p2 ^ pos) & 255) == 0) j = i + 1;
            }
            u_i0[nu] = s_ord[i];
            u_i1[nu] = (j >= 0) ? s_ord[j] : -1;
            u_r[nu]  = pos & 255;
            u_q0[nu] = (pos >> 8) - 1;
            u_q1[nu] = (j >= 0) ? ((s_pos[j] >> 8) - 1) : ((pos >> 8) - 1);
            nu++;
            i += (j >= 0) ? 2 : 1;
        }
        s_cnt[0] = nu;
        s_cnt[1] = nc;
    }
    __syncthreads();
    const int nu = s_cnt[0], nc = s_cnt[1];
    int all = 0;

    // copies (rare: pos < 256)
    for (int k = 0; k < nc; k++) {
        int ci = c_ci[k];
        int e = s_pos[ci] - 1;
        if (t == 0) {
            if (!all) all = all_done(E);
            if (!all) flag_wait(e, E);
        }
        __syncthreads();
        const float* src = g_U + (size_t)e * MSZ;
        float* C = out + (size_t)s_ord[ci] * MSZ;
        for (int e2 = t * 4; e2 < MSZ; e2 += 2048) {
            float4 v = __ldcg((const float4*)&src[e2]);
            *(float4*)&C[e2] = v;
        }
    }

    // matmul units (2-slot ring, t0-inline prefetch, all-done fast path)
    if (t == 0) {
        if (!all) all = all_done(E);
        if (nu > 0) load_unit(sb, 0, u_r[0], u_q0[0], u_q1[0], u_i1[0] >= 0, E, all);
        if (nu > 1) {
            if (!all) all = all_done(E);
            load_unit(sb, 1, u_r[1], u_q0[1], u_q1[1], u_i1[1] >= 0, E, all);
        }
    }
    const int wid = t >> 5, lane = t & 31, wr = wid >> 2, wc = wid & 3;
    for (int u = 0; u < nu; u++) {
        int s = u & 1, rd = u >> 1;
        uint32_t basep = sb + HDR + (uint32_t)s * SLOT_SZ;
        int pair = (u_i1[u] >= 0);
        float acc0[2][4][4], acc1[2][4][4];
#pragma unroll
        for (int a = 0; a < 2; a++)
#pragma unroll
            for (int bq = 0; bq < 4; bq++)
#pragma unroll
                for (int c = 0; c < 4; c++) { acc0[a][bq][c] = 0.0f; acc1[a][bq][c] = 0.0f; }

        MBARRIER_WAIT_PARITY(sb + s * 16, rd & 1);
        prodS2(basep, basep + 32768, basep + 65536, wr, wc, lane, pair, acc0, acc1);
        MBARRIER_ARRIVE(sb + s * 16 + 8);
        if (t == 0 && u + 2 < nu) {
            MBARRIER_WAIT_PARITY(sb + s * 16 + 8, rd & 1);
            if (!all) all = all_done(E);
            load_unit(sb, s, u_r[u + 2], u_q0[u + 2], u_q1[u + 2], u_i1[u + 2] >= 0, E, all);
        }
        store_fragS(out + (size_t)u_i0[u] * MSZ, wr, wc, lane, acc0);
        if (pair) store_fragS(out + (size_t)u_i1[u] * MSZ, wr, wc, lane, acc1);
    }
}

// ===========================================================================
extern "C" void kernel_launch(void* const* d_in, const int* in_sizes, int n_in,
                              void* d_out, int out_size) {
    const int* uniq = (const int*)d_in[0];
    const float* P  = (const float*)d_in[1];
    float* out = (float*)d_out;
    int n = in_sizes[0];

    k_epoch<<<1, 1>>>();
    cudaFuncSetAttribute(k_mega, cudaFuncAttributeMaxDynamicSharedMemorySize, MEGA_SMEM);
    k_mega<<<NCTA, 512, MEGA_SMEM>>>(uniq, P, out, n);
}